// round 10
// baseline (speedup 1.0000x reference)
#include <cuda_runtime.h>
#include <cuda_bf16.h>
#include <cuda_fp16.h>
#include <cstdint>
#include <math.h>

#define Bb   4
#define Ls   2048
#define Dm   1024
#define Hh   16
#define DPH  64
#define STR  40     // padded row stride (elems) for 32-col 16-bit tiles
#define VSTR 136    // V smem row stride in halves (128 data + 8 pad)

// ---------------- scratch (__device__ globals; allocation is forbidden) ----------------
__device__ __half g_pe[268435456];                 // e = exp(S) fp16 (512 MB), [bh][q][k]
__device__ __nv_bfloat16 g_xhi[3 * 8388608];       // inputs k,v,q split hi
__device__ __nv_bfloat16 g_xlo[3 * 8388608];
__device__ __nv_bfloat16 g_whi[4 * 1048576];       // kqv_w (3M) + fin_w (1M) hi
__device__ __nv_bfloat16 g_wlo[4 * 1048576];
__device__ __nv_bfloat16 g_qhi[8388608], g_qlo[8388608];   // q proj head-major [bh][l][d]
__device__ __nv_bfloat16 g_khi[8388608], g_klo[8388608];   // k proj head-major
__device__ __half g_vhi[8388608], g_vlo[8388608];          // v proj TRANSPOSED [bh][d][l], fp16 hi/lo
__device__ __nv_bfloat16 g_chi[8388608], g_clo[8388608];   // ctx [m][1024]
__device__ float g_iz[Bb * Hh * Ls];               // 1 / sum(exp(s)) per row
__device__ uint32_t g_mbits[Bb * Ls * Ls / 32];    // bit-packed attn_mask (2 MB)

// ============================ PTX helpers (sm_80+, valid on compute_103) ============================
__device__ __forceinline__ uint32_t saddr(const void* p) {
    return (uint32_t)__cvta_generic_to_shared(p);
}
__device__ __forceinline__ void ldsm4(uint32_t addr, uint32_t* r) {
    asm volatile("ldmatrix.sync.aligned.m8n8.x4.shared.b16 {%0,%1,%2,%3}, [%4];"
        : "=r"(r[0]), "=r"(r[1]), "=r"(r[2]), "=r"(r[3]) : "r"(addr));
}
__device__ __forceinline__ void mma16816(float* c, const uint32_t* a, const uint32_t* b) {
    asm volatile(
        "mma.sync.aligned.m16n8k16.row.col.f32.bf16.bf16.f32 "
        "{%0,%1,%2,%3},{%4,%5,%6,%7},{%8,%9},{%0,%1,%2,%3};"
        : "+f"(c[0]), "+f"(c[1]), "+f"(c[2]), "+f"(c[3])
        : "r"(a[0]), "r"(a[1]), "r"(a[2]), "r"(a[3]), "r"(b[0]), "r"(b[1]));
}
__device__ __forceinline__ void mma16816h(float* c, const uint32_t* a, const uint32_t* b) {
    asm volatile(
        "mma.sync.aligned.m16n8k16.row.col.f32.f16.f16.f32 "
        "{%0,%1,%2,%3},{%4,%5,%6,%7},{%8,%9},{%0,%1,%2,%3};"
        : "+f"(c[0]), "+f"(c[1]), "+f"(c[2]), "+f"(c[3])
        : "r"(a[0]), "r"(a[1]), "r"(a[2]), "r"(a[3]), "r"(b[0]), "r"(b[1]));
}
__device__ __forceinline__ void cpasync16(void* smem, const void* gmem) {
    asm volatile("cp.async.cg.shared.global [%0], [%1], 16;"
        :: "r"(saddr(smem)), "l"(gmem));
}
#define CP_COMMIT() asm volatile("cp.async.commit_group;")
#define CP_WAIT1()  asm volatile("cp.async.wait_group 1;")
#define CP_WAIT0()  asm volatile("cp.async.wait_group 0;")
#define SW(x) ((x) ^ (((x) >> 3) & 0x70))

__device__ __forceinline__ void split1(float v, __nv_bfloat16& h, __nv_bfloat16& l) {
    h = __float2bfloat16_rn(v);
    l = __float2bfloat16_rn(v - __bfloat162float(h));
}
__device__ __forceinline__ void split1h(float v, __half& h, __half& l) {
    h = __float2half_rn(v);
    l = __float2half_rn(v - __half2float(h));
}
__device__ __forceinline__ uint32_t packh2(float a, float b) {
    const __half2 h = __floats2half2_rn(a, b);
    return *(const uint32_t*)&h;
}

// =====================================================================================
// fp32 -> bf16 hi/lo split (linear). One thread = 4 elements.
// =====================================================================================
__global__ void __launch_bounds__(256) convsplit(const float* __restrict__ src,
                                                 __nv_bfloat16* __restrict__ hi,
                                                 __nv_bfloat16* __restrict__ lo)
{
    const size_t i4 = ((size_t)blockIdx.x * 256 + threadIdx.x) * 4;
    float4 v = *(const float4*)(src + i4);
    __nv_bfloat16 h0, h1, h2, h3, l0, l1, l2, l3;
    split1(v.x, h0, l0); split1(v.y, h1, l1); split1(v.z, h2, l2); split1(v.w, h3, l3);
    __nv_bfloat162 a, b;
    a.x = h0; a.y = h1; b.x = h2; b.y = h3;
    *(__nv_bfloat162*)(hi + i4) = a; *(__nv_bfloat162*)(hi + i4 + 2) = b;
    a.x = l0; a.y = l1; b.x = l2; b.y = l3;
    *(__nv_bfloat162*)(lo + i4) = a; *(__nv_bfloat162*)(lo + i4 + 2) = b;
}

// =====================================================================================
// Pack attn_mask int32 -> bits.
// =====================================================================================
__global__ void __launch_bounds__(256) packmask(const int* __restrict__ mask)
{
    const size_t w = (size_t)blockIdx.x * 256 + threadIdx.x;
    const int* p = mask + w * 32;
    uint32_t v = 0;
    #pragma unroll
    for (int i = 0; i < 8; i++) {
        int4 m = *(const int4*)(p + 4 * i);
        v |= (uint32_t)(m.x != 0) << (4 * i);
        v |= (uint32_t)(m.y != 0) << (4 * i + 1);
        v |= (uint32_t)(m.z != 0) << (4 * i + 2);
        v |= (uint32_t)(m.w != 0) << (4 * i + 3);
    }
    g_mbits[w] = v;
}

// =====================================================================================
// GEMM 128x128: C = X @ W^T (+bias). X/W pre-split bf16 hi/lo [rows][1024].
// EPI 0: q/k proj -> head-major bf16 hi/lo, *scale.
// EPI 1: v proj  -> transposed [bh][d][l] fp16 hi/lo.
// EPI 2: final   -> fp32 out [m][1024] * qmask.
// =====================================================================================
template <int EPI>
__global__ void __launch_bounds__(256, 2) gemm_bf(const __nv_bfloat16* __restrict__ Xhi,
                                                  const __nv_bfloat16* __restrict__ Xlo,
                                                  const __nv_bfloat16* __restrict__ Whi,
                                                  const __nv_bfloat16* __restrict__ Wlo,
                                                  const float* __restrict__ bias,
                                                  const float* __restrict__ qmask,
                                                  float scale,
                                                  void* __restrict__ Yhi_,
                                                  void* __restrict__ Ylo_,
                                                  float* __restrict__ Yf)
{
    extern __shared__ char smraw[];
    __nv_bfloat16* sb = (__nv_bfloat16*)smraw;
    const int TILE_E = 128 * STR;

    const int tid = threadIdx.x, wid = tid >> 5, lane = tid & 31;
    const int mw = wid >> 2, nw = wid & 3;
    const int m0 = blockIdx.y * 128, n0 = blockIdx.x * 128;
    const int group = lane >> 2, tig = lane & 3;

    float acc[4][4][4] = {};

    auto stage_load = [&](int s, int k0) {
        __nv_bfloat16* base = sb + s * 4 * TILE_E;
        #pragma unroll
        for (int i = 0; i < 4; i++) {
            const int lin = tid + i * 256;
            const int r = lin >> 3, c = lin & 7;
            if (c < 4) {
                cpasync16(base + r * STR + c * 8,             Xhi + (size_t)(m0 + r) * Dm + k0 + c * 8);
                cpasync16(base + TILE_E + r * STR + c * 8,    Xlo + (size_t)(m0 + r) * Dm + k0 + c * 8);
            } else {
                const int cc = c - 4;
                cpasync16(base + 2 * TILE_E + r * STR + cc * 8, Whi + (size_t)(n0 + r) * Dm + k0 + cc * 8);
                cpasync16(base + 3 * TILE_E + r * STR + cc * 8, Wlo + (size_t)(n0 + r) * Dm + k0 + cc * 8);
            }
        }
        CP_COMMIT();
    };

    stage_load(0, 0);

    for (int kc = 0; kc < 32; kc++) {
        if (kc < 31) { stage_load((kc + 1) & 1, (kc + 1) * 32); CP_WAIT1(); }
        else CP_WAIT0();
        __syncthreads();
        __nv_bfloat16* base = sb + (kc & 1) * 4 * TILE_E;
        __nv_bfloat16* sXhi = base;
        __nv_bfloat16* sXlo = base + TILE_E;
        __nv_bfloat16* sWhi = base + 2 * TILE_E;
        __nv_bfloat16* sWlo = base + 3 * TILE_E;
        #pragma unroll
        for (int kk = 0; kk < 32; kk += 16) {
            uint32_t ah[4][4], al[4][4], bh[4][2], bl[4][2];
            const int arow = mw * 64 + ((lane >> 3) & 1) * 8 + (lane & 7);
            const int acol = kk + (lane >> 4) * 8;
            #pragma unroll
            for (int i = 0; i < 4; i++) {
                ldsm4(saddr(sXhi + (arow + i * 16) * STR + acol), ah[i]);
                ldsm4(saddr(sXlo + (arow + i * 16) * STR + acol), al[i]);
            }
            const int brow = nw * 32 + (lane >> 4) * 8 + (lane & 7);
            const int bcol = kk + ((lane >> 3) & 1) * 8;
            #pragma unroll
            for (int jj = 0; jj < 2; jj++) {
                uint32_t t[4];
                ldsm4(saddr(sWhi + (brow + jj * 16) * STR + bcol), t);
                bh[2 * jj][0] = t[0]; bh[2 * jj][1] = t[1];
                bh[2 * jj + 1][0] = t[2]; bh[2 * jj + 1][1] = t[3];
                ldsm4(saddr(sWlo + (brow + jj * 16) * STR + bcol), t);
                bl[2 * jj][0] = t[0]; bl[2 * jj][1] = t[1];
                bl[2 * jj + 1][0] = t[2]; bl[2 * jj + 1][1] = t[3];
            }
            #pragma unroll
            for (int i = 0; i < 4; i++)
                #pragma unroll
                for (int j = 0; j < 4; j++) {
                    mma16816(acc[i][j], ah[i], bh[j]);
                    mma16816(acc[i][j], ah[i], bl[j]);
                    mma16816(acc[i][j], al[i], bh[j]);
                }
        }
        __syncthreads();
    }

    #pragma unroll
    for (int i = 0; i < 4; i++)
        #pragma unroll
        for (int j = 0; j < 4; j++) {
            const int c = n0 + nw * 32 + j * 8 + 2 * tig;
            const float2 bv = *(const float2*)(bias + c);
            #pragma unroll
            for (int hr = 0; hr < 2; hr++) {
                const int r = m0 + mw * 64 + i * 16 + group + hr * 8;
                const float o0 = (acc[i][j][2 * hr + 0] + bv.x) * (EPI == 2 ? qmask[r] : scale);
                const float o1 = (acc[i][j][2 * hr + 1] + bv.y) * (EPI == 2 ? qmask[r] : scale);
                if (EPI == 2) {
                    *(float2*)(Yf + (size_t)r * Dm + c) = make_float2(o0, o1);
                } else if (EPI == 0) {
                    const int h = c >> 6, d = c & 63;
                    const int bb = r >> 11, l = r & (Ls - 1);
                    __nv_bfloat16 h0, h1, l0, l1;
                    split1(o0, h0, l0); split1(o1, h1, l1);
                    const size_t idx = ((size_t)(bb * Hh + h) * Ls + l) * DPH + d;
                    __nv_bfloat162 ph; ph.x = h0; ph.y = h1;
                    __nv_bfloat162 pl; pl.x = l0; pl.y = l1;
                    *(__nv_bfloat162*)((__nv_bfloat16*)Yhi_ + idx) = ph;
                    *(__nv_bfloat162*)((__nv_bfloat16*)Ylo_ + idx) = pl;
                } else {
                    const int h = c >> 6, d = c & 63;
                    const int bb = r >> 11, l = r & (Ls - 1);
                    __half h0, h1, l0, l1;
                    split1h(o0, h0, l0); split1h(o1, h1, l1);
                    const size_t idx = ((size_t)(bb * Hh + h) * DPH + d) * Ls + l;
                    ((__half*)Yhi_)[idx] = h0; ((__half*)Ylo_)[idx] = l0;
                    ((__half*)Yhi_)[idx + Ls] = h1; ((__half*)Ylo_)[idx + Ls] = l1;
                }
            }
        }
}

// =====================================================================================
// Fused attention: per (q-tile 128, bh), loop 16 k-tiles of 128:
//   S = Q@K^T (bf16 hi/lo, 3-product) -> e = masked ? 0 : exp(s)
//   write e fp16 to g_pe (for avg), z += e
//   ctx += e @ V  (fp16 MMA, e accumulator fragments reused directly as A-fragments)
// Warps 4(m) x 2(k-slice). End: z-reduce -> g_iz; cross-warp ctx reduce -> *iz -> bf16
// hi/lo ctx. V tiles co-staged in the cp.async pipeline (pad-136 stride, conflict-free).
// =====================================================================================
__global__ void __launch_bounds__(256, 1) attn_kernel()
{
    extern __shared__ char smraw[];
    char* sQhi = smraw;
    char* sQlo = smraw + 16384;
    char* sK   = smraw + 32768;                     // 2 stages x (hi 16384 | lo 16384)
    char* sV   = smraw + 98304;                     // 2 stages x (hi 17408 | lo 17408)
    float* red_z   = (float*)(smraw + 167936);      // 2 x 128
    float* scratch = (float*)(smraw + 32768);       // reuse sK: 128 x 64 fp32 ctx reduce

    const int tid = threadIdx.x, wid = tid >> 5, lane = tid & 31;
    const int mw = wid >> 1, nw = wid & 1;
    const int m0 = blockIdx.x * 128;
    const int bh = blockIdx.y;
    const int b = bh >> 4, h = bh & 15;
    const int group = lane >> 2, tig = lane & 3;
    const __nv_bfloat16* Qhi = g_qhi + (size_t)bh * Ls * DPH;
    const __nv_bfloat16* Qlo = g_qlo + (size_t)bh * Ls * DPH;
    const __nv_bfloat16* Khi = g_khi + (size_t)bh * Ls * DPH;
    const __nv_bfloat16* Klo = g_klo + (size_t)bh * Ls * DPH;
    const __half* Vhi = g_vhi + (size_t)bh * DPH * Ls;
    const __half* Vlo = g_vlo + (size_t)bh * DPH * Ls;

    // Q tile once (SW128)
    #pragma unroll
    for (int i = 0; i < 4; i++) {
        const int lin = tid + i * 256;
        const int r = lin >> 3, ch = lin & 7;
        const uint32_t off = SW(r * 128 + ch * 16);
        cpasync16(sQhi + off, Qhi + (size_t)(m0 + r) * DPH + ch * 8);
        cpasync16(sQlo + off, Qlo + (size_t)(m0 + r) * DPH + ch * 8);
    }
    CP_COMMIT();

    auto stage_load = [&](int s, int n0) {
        char* khb = sK + s * 32768;
        char* klb = khb + 16384;
        #pragma unroll
        for (int i = 0; i < 4; i++) {
            const int lin = tid + i * 256;
            const int r = lin >> 3, ch = lin & 7;
            const uint32_t off = SW(r * 128 + ch * 16);
            cpasync16(khb + off, Khi + (size_t)(n0 + r) * DPH + ch * 8);
            cpasync16(klb + off, Klo + (size_t)(n0 + r) * DPH + ch * 8);
        }
        __half* vhb = (__half*)(sV + s * 34816);
        __half* vlb = vhb + 8704;                    // 17408 bytes / 2
        const int vr = tid >> 2;
        #pragma unroll
        for (int ii = 0; ii < 4; ii++) {
            const int chunk = (tid & 3) * 4 + ii;
            cpasync16(vhb + vr * VSTR + chunk * 8, Vhi + (size_t)vr * Ls + n0 + chunk * 8);
            cpasync16(vlb + vr * VSTR + chunk * 8, Vlo + (size_t)vr * Ls + n0 + chunk * 8);
        }
        CP_COMMIT();
    };
    stage_load(0, 0);

    float ctx[2][8][4] = {};
    float zloc[2][2] = {};
    const uint32_t qhi_a = saddr(sQhi), qlo_a = saddr(sQlo);

    for (int nt = 0; nt < Ls / 128; nt++) {
        const int n0 = nt * 128;
        if (nt < Ls / 128 - 1) { stage_load((nt + 1) & 1, n0 + 128); CP_WAIT1(); }
        else CP_WAIT0();
        __syncthreads();

        uint32_t mb[2][2][2];
        #pragma unroll
        for (int i = 0; i < 2; i++)
            #pragma unroll
            for (int hr = 0; hr < 2; hr++) {
                const int r = m0 + mw * 32 + i * 16 + group + hr * 8;
                const size_t mbase = (size_t)(b * Ls + r) * (Ls / 32) + ((n0 + nw * 64) >> 5);
                mb[i][hr][0] = g_mbits[mbase];
                mb[i][hr][1] = g_mbits[mbase + 1];
            }

        const uint32_t khi_a = saddr(sK + (nt & 1) * 32768);
        const uint32_t klo_a = khi_a + 16384;

        // ---- QK ----
        float acc[2][8][4] = {};
        #pragma unroll
        for (int kk = 0; kk < DPH; kk += 16) {
            uint32_t ah[2][4], al[2][4], bh2[8][2], bl[8][2];
            const int arow = mw * 32 + ((lane >> 3) & 1) * 8 + (lane & 7);
            const int acol = kk + (lane >> 4) * 8;
            #pragma unroll
            for (int i = 0; i < 2; i++) {
                const uint32_t o = SW((arow + i * 16) * 128 + acol * 2);
                ldsm4(qhi_a + o, ah[i]);
                ldsm4(qlo_a + o, al[i]);
            }
            const int brow = nw * 64 + (lane >> 4) * 8 + (lane & 7);
            const int bcol = kk + ((lane >> 3) & 1) * 8;
            #pragma unroll
            for (int jj = 0; jj < 4; jj++) {
                const uint32_t o = SW((brow + jj * 16) * 128 + bcol * 2);
                uint32_t t[4];
                ldsm4(khi_a + o, t);
                bh2[2 * jj][0] = t[0]; bh2[2 * jj][1] = t[1];
                bh2[2 * jj + 1][0] = t[2]; bh2[2 * jj + 1][1] = t[3];
                ldsm4(klo_a + o, t);
                bl[2 * jj][0] = t[0]; bl[2 * jj][1] = t[1];
                bl[2 * jj + 1][0] = t[2]; bl[2 * jj + 1][1] = t[3];
            }
            #pragma unroll
            for (int i = 0; i < 2; i++)
                #pragma unroll
                for (int j = 0; j < 8; j++) {
                    mma16816(acc[i][j], ah[i], bh2[j]);
                    mma16816(acc[i][j], ah[i], bl[j]);
                    mma16816(acc[i][j], al[i], bh2[j]);
                }
        }

        // ---- e = exp(s) (masked -> 0), write to gmem, z accumulate, keep in acc ----
        #pragma unroll
        for (int i = 0; i < 2; i++)
            #pragma unroll
            for (int hr = 0; hr < 2; hr++) {
                const int r = m0 + mw * 32 + i * 16 + group + hr * 8;
                float zadd = 0.f;
                #pragma unroll
                for (int j = 0; j < 8; j++) {
                    const uint32_t bits = mb[i][hr][j >> 2];
                    const int bpos = (j & 3) * 8 + 2 * tig;
                    const int c = n0 + nw * 64 + j * 8 + 2 * tig;
                    const float e0 = ((bits >> bpos) & 1u) ? 0.f : __expf(acc[i][j][2 * hr + 0]);
                    const float e1 = ((bits >> (bpos + 1)) & 1u) ? 0.f : __expf(acc[i][j][2 * hr + 1]);
                    acc[i][j][2 * hr + 0] = e0;
                    acc[i][j][2 * hr + 1] = e1;
                    *(__half2*)(g_pe + ((size_t)bh * Ls + r) * Ls + c) = __floats2half2_rn(e0, e1);
                    zadd += e0 + e1;
                }
                zloc[i][hr] += zadd;
            }

        // ---- PV: ctx += e @ V over this warp's 64-k slice ----
        const uint32_t vhi_a = saddr(sV + (nt & 1) * 34816);
        const uint32_t vlo_a = vhi_a + 17408;
        #pragma unroll
        for (int s = 0; s < 4; s++) {
            uint32_t af[2][4];
            #pragma unroll
            for (int i = 0; i < 2; i++) {
                af[i][0] = packh2(acc[i][2 * s][0], acc[i][2 * s][1]);
                af[i][1] = packh2(acc[i][2 * s][2], acc[i][2 * s][3]);
                af[i][2] = packh2(acc[i][2 * s + 1][0], acc[i][2 * s + 1][1]);
                af[i][3] = packh2(acc[i][2 * s + 1][2], acc[i][2 * s + 1][3]);
            }
            const int bcol = nw * 64 + s * 16 + ((lane >> 3) & 1) * 8;   // k within tile
            uint32_t vh[8][2], vl[8][2];
            #pragma unroll
            for (int jj = 0; jj < 4; jj++) {
                const int brow = jj * 16 + (lane >> 4) * 8 + (lane & 7); // d
                uint32_t t[4];
                ldsm4(vhi_a + (brow * VSTR + bcol) * 2, t);
                vh[2 * jj][0] = t[0]; vh[2 * jj][1] = t[1];
                vh[2 * jj + 1][0] = t[2]; vh[2 * jj + 1][1] = t[3];
                ldsm4(vlo_a + (brow * VSTR + bcol) * 2, t);
                vl[2 * jj][0] = t[0]; vl[2 * jj][1] = t[1];
                vl[2 * jj + 1][0] = t[2]; vl[2 * jj + 1][1] = t[3];
            }
            #pragma unroll
            for (int i = 0; i < 2; i++)
                #pragma unroll
                for (int dj = 0; dj < 8; dj++) {
                    mma16816h(ctx[i][dj], af[i], vh[dj]);
                    mma16816h(ctx[i][dj], af[i], vl[dj]);
                }
        }
        __syncthreads();
    }

    // ---- z reduce -> g_iz + smem iz ----
    #pragma unroll
    for (int i = 0; i < 2; i++)
        #pragma unroll
        for (int hr = 0; hr < 2; hr++) {
            float z = zloc[i][hr];
            z += __shfl_xor_sync(0xFFFFFFFFu, z, 1);
            z += __shfl_xor_sync(0xFFFFFFFFu, z, 2);
            if (tig == 0) {
                const int rloc = mw * 32 + i * 16 + hr * 8 + group;
                red_z[nw * 128 + rloc] = z;
            }
        }
    __syncthreads();
    float izval = 0.f;
    if (tid < 128) {
        const float z = red_z[tid] + red_z[128 + tid];
        izval = 1.f / z;
        g_iz[(size_t)bh * Ls + m0 + tid] = izval;
    }
    __syncthreads();
    if (tid < 128) red_z[tid] = izval;

    // ---- cross-warp ctx reduce (nw pairs) ----
    if (nw == 1) {
        #pragma unroll
        for (int i = 0; i < 2; i++)
            #pragma unroll
            for (int dj = 0; dj < 8; dj++)
                #pragma unroll
                for (int hr = 0; hr < 2; hr++) {
                    const int rl = mw * 32 + i * 16 + group + hr * 8;
                    const int c = dj * 8 + 2 * tig;
                    *(float2*)(scratch + rl * 64 + c)
                        = make_float2(ctx[i][dj][2 * hr + 0], ctx[i][dj][2 * hr + 1]);
                }
    }
    __syncthreads();
    if (nw == 0) {
        #pragma unroll
        for (int i = 0; i < 2; i++)
            #pragma unroll
            for (int dj = 0; dj < 8; dj++)
                #pragma unroll
                for (int hr = 0; hr < 2; hr++) {
                    const int rl = mw * 32 + i * 16 + group + hr * 8;
                    const int c = dj * 8 + 2 * tig;
                    const float2 oth = *(const float2*)(scratch + rl * 64 + c);
                    const float iz = red_z[rl];
                    const float o0 = (ctx[i][dj][2 * hr + 0] + oth.x) * iz;
                    const float o1 = (ctx[i][dj][2 * hr + 1] + oth.y) * iz;
                    const size_t idx = (size_t)(b * Ls + m0 + rl) * Dm + h * 64 + c;
                    __nv_bfloat16 h0, h1, l0, l1;
                    split1(o0, h0, l0); split1(o1, h1, l1);
                    __nv_bfloat162 ph; ph.x = h0; ph.y = h1;
                    __nv_bfloat162 pl; pl.x = l0; pl.y = l1;
                    *(__nv_bfloat162*)(g_chi + idx) = ph;
                    *(__nv_bfloat162*)(g_clo + idx) = pl;
                }
    }
}

// =====================================================================================
// avg: attn_avg[b,q,k] = qmask/Hh * sum_h e*iz_h.  Read-only fp16 stream.
// =====================================================================================
__global__ void __launch_bounds__(256) avg_kernel(const float* __restrict__ qmask,
                                                  float* __restrict__ avg_out)
{
    const int tid = threadIdx.x;
    const int tx = tid & 15, ty = tid >> 4;
    const int k0 = blockIdx.x * 64;
    const int q0 = blockIdx.y * 64;
    const int b = blockIdx.z;

    float sum[4][4] = {};
    for (int h = 0; h < Hh; h++) {
        const int bhh = b * Hh + h;
        #pragma unroll
        for (int i = 0; i < 4; i++) {
            const int q = q0 + ty * 4 + i;
            const float iz = g_iz[(size_t)bhh * Ls + q];
            const size_t so = ((size_t)bhh * Ls + q) * Ls + k0 + tx * 4;
            const __half2 e01 = *(const __half2*)(g_pe + so);
            const __half2 e23 = *(const __half2*)(g_pe + so + 2);
            const float2 f01 = __half22float2(e01);
            const float2 f23 = __half22float2(e23);
            sum[i][0] = fmaf(f01.x, iz, sum[i][0]);
            sum[i][1] = fmaf(f01.y, iz, sum[i][1]);
            sum[i][2] = fmaf(f23.x, iz, sum[i][2]);
            sum[i][3] = fmaf(f23.y, iz, sum[i][3]);
        }
    }
    #pragma unroll
    for (int i = 0; i < 4; i++) {
        const int q = q0 + ty * 4 + i;
        const float qm = qmask[b * Ls + q] * (1.f / (float)Hh);
        float4 o;
        o.x = sum[i][0] * qm; o.y = sum[i][1] * qm; o.z = sum[i][2] * qm; o.w = sum[i][3] * qm;
        *(float4*)(avg_out + (size_t)(b * Ls + q) * Ls + k0 + tx * 4) = o;
    }
}

// =====================================================================================
// Launch. Inputs: k, v, q, attn_mask, query_mask, kqv_w, kqv_b, fin_w, fin_b
// =====================================================================================
extern "C" void kernel_launch(void* const* d_in, const int* in_sizes, int n_in,
                              void* d_out, int out_size)
{
    (void)in_sizes; (void)n_in; (void)out_size;
    const float* k_in  = (const float*)d_in[0];
    const float* v_in  = (const float*)d_in[1];
    const float* q_in  = (const float*)d_in[2];
    const int*   amask = (const int*)  d_in[3];
    const float* qmask = (const float*)d_in[4];
    const float* kqv_w = (const float*)d_in[5];
    const float* kqv_b = (const float*)d_in[6];
    const float* fin_w = (const float*)d_in[7];
    const float* fin_b = (const float*)d_in[8];
    float* out_ctx = (float*)d_out;
    float* out_avg = out_ctx + (size_t)Bb * Ls * Dm;

    __nv_bfloat16 *xhi, *xlo, *whi, *wlo, *qhi, *qlo, *khi, *klo, *chi, *clo;
    __half *vhi, *vlo;
    cudaGetSymbolAddress((void**)&xhi, g_xhi); cudaGetSymbolAddress((void**)&xlo, g_xlo);
    cudaGetSymbolAddress((void**)&whi, g_whi); cudaGetSymbolAddress((void**)&wlo, g_wlo);
    cudaGetSymbolAddress((void**)&qhi, g_qhi); cudaGetSymbolAddress((void**)&qlo, g_qlo);
    cudaGetSymbolAddress((void**)&khi, g_khi); cudaGetSymbolAddress((void**)&klo, g_klo);
    cudaGetSymbolAddress((void**)&vhi, g_vhi); cudaGetSymbolAddress((void**)&vlo, g_vlo);
    cudaGetSymbolAddress((void**)&chi, g_chi); cudaGetSymbolAddress((void**)&clo, g_clo);

    const int GSM  = 2 * 4 * 128 * STR * 2;      // 81920 B
    const int ATSM = 167936 + 1024;              // 168960 B
    static int attr_set = 0;
    if (!attr_set) {
        cudaFuncSetAttribute(gemm_bf<0>, cudaFuncAttributeMaxDynamicSharedMemorySize, GSM);
        cudaFuncSetAttribute(gemm_bf<1>, cudaFuncAttributeMaxDynamicSharedMemorySize, GSM);
        cudaFuncSetAttribute(gemm_bf<2>, cudaFuncAttributeMaxDynamicSharedMemorySize, GSM);
        cudaFuncSetAttribute(attn_kernel, cudaFuncAttributeMaxDynamicSharedMemorySize, ATSM);
        attr_set = 1;
    }

    // --- prologue: split inputs/weights, pack mask ---
    const int NIN = 8388608;
    convsplit<<<NIN / 1024, 256>>>(k_in, xhi,           xlo);
    convsplit<<<NIN / 1024, 256>>>(v_in, xhi + NIN,     xlo + NIN);
    convsplit<<<NIN / 1024, 256>>>(q_in, xhi + 2 * NIN, xlo + 2 * NIN);
    convsplit<<<(3 * 1048576) / 1024, 256>>>(kqv_w, whi,              wlo);
    convsplit<<<1048576 / 1024, 256>>>(fin_w, whi + 3 * 1048576, wlo + 3 * 1048576);
    packmask<<<(Bb * Ls * Ls / 32) / 256, 256>>>(amask);

    dim3 gg(Dm / 128, (Bb * Ls) / 128);    // (8, 64)
    gemm_bf<0><<<gg, 256, GSM>>>(xhi, xlo, whi, wlo, kqv_b, nullptr, 1.0f, khi, klo, nullptr);
    gemm_bf<0><<<gg, 256, GSM>>>(xhi + 2 * NIN, xlo + 2 * NIN, whi + 1048576, wlo + 1048576,
                                 kqv_b + Dm, nullptr, 0.125f, qhi, qlo, nullptr);
    gemm_bf<1><<<gg, 256, GSM>>>(xhi + NIN, xlo + NIN, whi + 2 * 1048576, wlo + 2 * 1048576,
                                 kqv_b + 2 * Dm, nullptr, 1.0f, vhi, vlo, nullptr);

    attn_kernel<<<dim3(Ls / 128, Bb * Hh), 256, ATSM>>>();

    avg_kernel<<<dim3(Ls / 64, Ls / 64, Bb), 256>>>(qmask, out_avg);

    gemm_bf<2><<<gg, 256, GSM>>>(chi, clo, whi + 3 * 1048576, wlo + 3 * 1048576,
                                 fin_b, qmask, 1.0f, nullptr, nullptr, out_ctx);
}

// round 12
// speedup vs baseline: 1.1159x; 1.1159x over previous
#include <cuda_runtime.h>
#include <cuda_bf16.h>
#include <cuda_fp16.h>
#include <cstdint>
#include <math.h>

#define Bb   4
#define Ls   2048
#define Dm   1024
#define Hh   16
#define DPH  64
#define STR  40     // padded row stride (elems) for 32-col 16-bit tiles
#define STR2 72     // padded row stride for 64-col tiles (pv)

// ---------------- scratch (__device__ globals; allocation is forbidden) ----------------
__device__ __half g_pe[268435456];                 // e = exp(S) fp16 (512 MB), [bh][q][k]
__device__ __nv_bfloat16 g_xhi[3 * 8388608];       // inputs k,v,q split hi
__device__ __nv_bfloat16 g_xlo[3 * 8388608];
__device__ __nv_bfloat16 g_whi[4 * 1048576];       // kqv_w (3M) + fin_w (1M) hi
__device__ __nv_bfloat16 g_wlo[4 * 1048576];
__device__ __nv_bfloat16 g_qhi[8388608], g_qlo[8388608];   // q proj head-major [bh][l][d]
__device__ __nv_bfloat16 g_khi[8388608], g_klo[8388608];   // k proj head-major
__device__ __half g_vhi[8388608], g_vlo[8388608];          // v proj TRANSPOSED [bh][d][l], fp16 hi/lo
__device__ __nv_bfloat16 g_chi[8388608], g_clo[8388608];   // ctx [m][1024]
__device__ float g_iz[Bb * Hh * Ls];               // 1 / sum(exp(s)) per row
__device__ uint32_t g_mbits[Bb * Ls * Ls / 32];    // bit-packed attn_mask (2 MB)

// ============================ PTX helpers (sm_80+, valid on compute_103) ============================
__device__ __forceinline__ uint32_t saddr(const void* p) {
    return (uint32_t)__cvta_generic_to_shared(p);
}
__device__ __forceinline__ void ldsm4(uint32_t addr, uint32_t* r) {
    asm volatile("ldmatrix.sync.aligned.m8n8.x4.shared.b16 {%0,%1,%2,%3}, [%4];"
        : "=r"(r[0]), "=r"(r[1]), "=r"(r[2]), "=r"(r[3]) : "r"(addr));
}
__device__ __forceinline__ void mma16816(float* c, const uint32_t* a, const uint32_t* b) {
    asm volatile(
        "mma.sync.aligned.m16n8k16.row.col.f32.bf16.bf16.f32 "
        "{%0,%1,%2,%3},{%4,%5,%6,%7},{%8,%9},{%0,%1,%2,%3};"
        : "+f"(c[0]), "+f"(c[1]), "+f"(c[2]), "+f"(c[3])
        : "r"(a[0]), "r"(a[1]), "r"(a[2]), "r"(a[3]), "r"(b[0]), "r"(b[1]));
}
__device__ __forceinline__ void mma16816h(float* c, const uint32_t* a, const uint32_t* b) {
    asm volatile(
        "mma.sync.aligned.m16n8k16.row.col.f32.f16.f16.f32 "
        "{%0,%1,%2,%3},{%4,%5,%6,%7},{%8,%9},{%0,%1,%2,%3};"
        : "+f"(c[0]), "+f"(c[1]), "+f"(c[2]), "+f"(c[3])
        : "r"(a[0]), "r"(a[1]), "r"(a[2]), "r"(a[3]), "r"(b[0]), "r"(b[1]));
}
__device__ __forceinline__ void cpasync16(void* smem, const void* gmem) {
    asm volatile("cp.async.cg.shared.global [%0], [%1], 16;"
        :: "r"(saddr(smem)), "l"(gmem));
}
#define CP_COMMIT() asm volatile("cp.async.commit_group;")
#define CP_WAIT1()  asm volatile("cp.async.wait_group 1;")
#define CP_WAIT0()  asm volatile("cp.async.wait_group 0;")
#define SW(x) ((x) ^ (((x) >> 3) & 0x70))

__device__ __forceinline__ void split1(float v, __nv_bfloat16& h, __nv_bfloat16& l) {
    h = __float2bfloat16_rn(v);
    l = __float2bfloat16_rn(v - __bfloat162float(h));
}
__device__ __forceinline__ void split1h(float v, __half& h, __half& l) {
    h = __float2half_rn(v);
    l = __float2half_rn(v - __half2float(h));
}

// =====================================================================================
// fp32 -> bf16 hi/lo split (linear). One thread = 4 elements.
// =====================================================================================
__global__ void __launch_bounds__(256) convsplit(const float* __restrict__ src,
                                                 __nv_bfloat16* __restrict__ hi,
                                                 __nv_bfloat16* __restrict__ lo)
{
    const size_t i4 = ((size_t)blockIdx.x * 256 + threadIdx.x) * 4;
    float4 v = *(const float4*)(src + i4);
    __nv_bfloat16 h0, h1, h2, h3, l0, l1, l2, l3;
    split1(v.x, h0, l0); split1(v.y, h1, l1); split1(v.z, h2, l2); split1(v.w, h3, l3);
    __nv_bfloat162 a, b;
    a.x = h0; a.y = h1; b.x = h2; b.y = h3;
    *(__nv_bfloat162*)(hi + i4) = a; *(__nv_bfloat162*)(hi + i4 + 2) = b;
    a.x = l0; a.y = l1; b.x = l2; b.y = l3;
    *(__nv_bfloat162*)(lo + i4) = a; *(__nv_bfloat162*)(lo + i4 + 2) = b;
}

// =====================================================================================
// Pack attn_mask int32 -> bits.
// =====================================================================================
__global__ void __launch_bounds__(256) packmask(const int* __restrict__ mask)
{
    const size_t w = (size_t)blockIdx.x * 256 + threadIdx.x;
    const int* p = mask + w * 32;
    uint32_t v = 0;
    #pragma unroll
    for (int i = 0; i < 8; i++) {
        int4 m = *(const int4*)(p + 4 * i);
        v |= (uint32_t)(m.x != 0) << (4 * i);
        v |= (uint32_t)(m.y != 0) << (4 * i + 1);
        v |= (uint32_t)(m.z != 0) << (4 * i + 2);
        v |= (uint32_t)(m.w != 0) << (4 * i + 3);
    }
    g_mbits[w] = v;
}

// =====================================================================================
// GEMM 128x128: C = X @ W^T (+bias). X/W pre-split bf16 hi/lo [rows][1024].
// EPI 0: q/k proj -> head-major bf16 hi/lo, *scale.
// EPI 1: v proj  -> transposed [bh][d][l] fp16 hi/lo.
// EPI 2: final   -> fp32 out [m][1024] * qmask.
// =====================================================================================
template <int EPI>
__global__ void __launch_bounds__(256, 2) gemm_bf(const __nv_bfloat16* __restrict__ Xhi,
                                                  const __nv_bfloat16* __restrict__ Xlo,
                                                  const __nv_bfloat16* __restrict__ Whi,
                                                  const __nv_bfloat16* __restrict__ Wlo,
                                                  const float* __restrict__ bias,
                                                  const float* __restrict__ qmask,
                                                  float scale,
                                                  void* __restrict__ Yhi_,
                                                  void* __restrict__ Ylo_,
                                                  float* __restrict__ Yf)
{
    extern __shared__ char smraw[];
    __nv_bfloat16* sb = (__nv_bfloat16*)smraw;
    const int TILE_E = 128 * STR;

    const int tid = threadIdx.x, wid = tid >> 5, lane = tid & 31;
    const int mw = wid >> 2, nw = wid & 3;
    const int m0 = blockIdx.y * 128, n0 = blockIdx.x * 128;
    const int group = lane >> 2, tig = lane & 3;

    float acc[4][4][4] = {};

    auto stage_load = [&](int s, int k0) {
        __nv_bfloat16* base = sb + s * 4 * TILE_E;
        #pragma unroll
        for (int i = 0; i < 4; i++) {
            const int lin = tid + i * 256;
            const int r = lin >> 3, c = lin & 7;
            if (c < 4) {
                cpasync16(base + r * STR + c * 8,             Xhi + (size_t)(m0 + r) * Dm + k0 + c * 8);
                cpasync16(base + TILE_E + r * STR + c * 8,    Xlo + (size_t)(m0 + r) * Dm + k0 + c * 8);
            } else {
                const int cc = c - 4;
                cpasync16(base + 2 * TILE_E + r * STR + cc * 8, Whi + (size_t)(n0 + r) * Dm + k0 + cc * 8);
                cpasync16(base + 3 * TILE_E + r * STR + cc * 8, Wlo + (size_t)(n0 + r) * Dm + k0 + cc * 8);
            }
        }
        CP_COMMIT();
    };

    stage_load(0, 0);

    for (int kc = 0; kc < 32; kc++) {
        if (kc < 31) { stage_load((kc + 1) & 1, (kc + 1) * 32); CP_WAIT1(); }
        else CP_WAIT0();
        __syncthreads();
        __nv_bfloat16* base = sb + (kc & 1) * 4 * TILE_E;
        __nv_bfloat16* sXhi = base;
        __nv_bfloat16* sXlo = base + TILE_E;
        __nv_bfloat16* sWhi = base + 2 * TILE_E;
        __nv_bfloat16* sWlo = base + 3 * TILE_E;
        #pragma unroll
        for (int kk = 0; kk < 32; kk += 16) {
            uint32_t ah[4][4], al[4][4], bh[4][2], bl[4][2];
            const int arow = mw * 64 + ((lane >> 3) & 1) * 8 + (lane & 7);
            const int acol = kk + (lane >> 4) * 8;
            #pragma unroll
            for (int i = 0; i < 4; i++) {
                ldsm4(saddr(sXhi + (arow + i * 16) * STR + acol), ah[i]);
                ldsm4(saddr(sXlo + (arow + i * 16) * STR + acol), al[i]);
            }
            const int brow = nw * 32 + (lane >> 4) * 8 + (lane & 7);
            const int bcol = kk + ((lane >> 3) & 1) * 8;
            #pragma unroll
            for (int jj = 0; jj < 2; jj++) {
                uint32_t t[4];
                ldsm4(saddr(sWhi + (brow + jj * 16) * STR + bcol), t);
                bh[2 * jj][0] = t[0]; bh[2 * jj][1] = t[1];
                bh[2 * jj + 1][0] = t[2]; bh[2 * jj + 1][1] = t[3];
                ldsm4(saddr(sWlo + (brow + jj * 16) * STR + bcol), t);
                bl[2 * jj][0] = t[0]; bl[2 * jj][1] = t[1];
                bl[2 * jj + 1][0] = t[2]; bl[2 * jj + 1][1] = t[3];
            }
            #pragma unroll
            for (int i = 0; i < 4; i++)
                #pragma unroll
                for (int j = 0; j < 4; j++) {
                    mma16816(acc[i][j], ah[i], bh[j]);
                    mma16816(acc[i][j], ah[i], bl[j]);
                    mma16816(acc[i][j], al[i], bh[j]);
                }
        }
        __syncthreads();
    }

    #pragma unroll
    for (int i = 0; i < 4; i++)
        #pragma unroll
        for (int j = 0; j < 4; j++) {
            const int c = n0 + nw * 32 + j * 8 + 2 * tig;
            const float2 bv = *(const float2*)(bias + c);
            #pragma unroll
            for (int hr = 0; hr < 2; hr++) {
                const int r = m0 + mw * 64 + i * 16 + group + hr * 8;
                const float o0 = (acc[i][j][2 * hr + 0] + bv.x) * (EPI == 2 ? qmask[r] : scale);
                const float o1 = (acc[i][j][2 * hr + 1] + bv.y) * (EPI == 2 ? qmask[r] : scale);
                if (EPI == 2) {
                    *(float2*)(Yf + (size_t)r * Dm + c) = make_float2(o0, o1);
                } else if (EPI == 0) {
                    const int h = c >> 6, d = c & 63;
                    const int bb = r >> 11, l = r & (Ls - 1);
                    __nv_bfloat16 h0, h1, l0, l1;
                    split1(o0, h0, l0); split1(o1, h1, l1);
                    const size_t idx = ((size_t)(bb * Hh + h) * Ls + l) * DPH + d;
                    __nv_bfloat162 ph; ph.x = h0; ph.y = h1;
                    __nv_bfloat162 pl; pl.x = l0; pl.y = l1;
                    *(__nv_bfloat162*)((__nv_bfloat16*)Yhi_ + idx) = ph;
                    *(__nv_bfloat162*)((__nv_bfloat16*)Ylo_ + idx) = pl;
                } else {
                    const int h = c >> 6, d = c & 63;
                    const int bb = r >> 11, l = r & (Ls - 1);
                    __half h0, h1, l0, l1;
                    split1h(o0, h0, l0); split1h(o1, h1, l1);
                    const size_t idx = ((size_t)(bb * Hh + h) * DPH + d) * Ls + l;
                    ((__half*)Yhi_)[idx] = h0; ((__half*)Ylo_)[idx] = l0;
                    ((__half*)Yhi_)[idx + Ls] = h1; ((__half*)Ylo_)[idx + Ls] = l1;
                }
            }
        }
}

// =====================================================================================
// Fused QK + exp + z. Block = (q-tile 128, bh). Loops 16 k-tiles: S = Q@K^T,
// e = masked ? 0 : exp(s) (no max shift — |s| <~ 6; softmax shift-invariant),
// write e as fp16 into g_pe, accumulate z = sum(e), store iz = 1/z.
// =====================================================================================
__global__ void __launch_bounds__(256, 2) qk_kernel()
{
    extern __shared__ char smraw[];
    char* sQhi = smraw;
    char* sQlo = smraw + 16384;
    char* sK   = smraw + 32768;                     // [stage][hi 16384 | lo 16384]
    float* red_z = (float*)(smraw + 98304);

    const int tid = threadIdx.x, wid = tid >> 5, lane = tid & 31;
    const int mw = wid >> 2, nw = wid & 3;
    const int m0 = blockIdx.x * 128;
    const int bh = blockIdx.y;
    const int b = bh >> 4;
    const int group = lane >> 2, tig = lane & 3;
    const __nv_bfloat16* Qhi = g_qhi + (size_t)bh * Ls * DPH;
    const __nv_bfloat16* Qlo = g_qlo + (size_t)bh * Ls * DPH;
    const __nv_bfloat16* Khi = g_khi + (size_t)bh * Ls * DPH;
    const __nv_bfloat16* Klo = g_klo + (size_t)bh * Ls * DPH;

    #pragma unroll
    for (int i = 0; i < 4; i++) {
        const int lin = tid + i * 256;
        const int r = lin >> 3, ch = lin & 7;
        const uint32_t off = SW(r * 128 + ch * 16);
        cpasync16(sQhi + off, Qhi + (size_t)(m0 + r) * DPH + ch * 8);
        cpasync16(sQlo + off, Qlo + (size_t)(m0 + r) * DPH + ch * 8);
    }
    CP_COMMIT();

    auto kload = [&](int s, int n0) {
        char* khb = sK + s * 32768;
        char* klb = khb + 16384;
        #pragma unroll
        for (int i = 0; i < 4; i++) {
            const int lin = tid + i * 256;
            const int r = lin >> 3, ch = lin & 7;
            const uint32_t off = SW(r * 128 + ch * 16);
            cpasync16(khb + off, Khi + (size_t)(n0 + r) * DPH + ch * 8);
            cpasync16(klb + off, Klo + (size_t)(n0 + r) * DPH + ch * 8);
        }
        CP_COMMIT();
    };
    kload(0, 0);

    float zloc[4][2] = {};

    const uint32_t qhi_a = saddr(sQhi), qlo_a = saddr(sQlo);

    for (int nt = 0; nt < Ls / 128; nt++) {
        const int n0 = nt * 128;
        if (nt < Ls / 128 - 1) { kload((nt + 1) & 1, n0 + 128); CP_WAIT1(); }
        else CP_WAIT0();
        __syncthreads();

        uint32_t mb[4][2];
        #pragma unroll
        for (int i = 0; i < 4; i++)
            #pragma unroll
            for (int hr = 0; hr < 2; hr++) {
                const int r = m0 + mw * 64 + i * 16 + group + hr * 8;
                mb[i][hr] = g_mbits[(size_t)(b * Ls + r) * (Ls / 32) + ((n0 + nw * 32) >> 5)];
            }

        const uint32_t khi_a = saddr(sK + (nt & 1) * 32768);
        const uint32_t klo_a = khi_a + 16384;

        float acc[4][4][4] = {};
        #pragma unroll
        for (int kk = 0; kk < DPH; kk += 16) {
            uint32_t ah[4][4], al[4][4], bh2[4][2], bl[4][2];
            const int arow = mw * 64 + ((lane >> 3) & 1) * 8 + (lane & 7);
            const int acol = kk + (lane >> 4) * 8;
            #pragma unroll
            for (int i = 0; i < 4; i++) {
                const uint32_t o = SW((arow + i * 16) * 128 + acol * 2);
                ldsm4(qhi_a + o, ah[i]);
                ldsm4(qlo_a + o, al[i]);
            }
            const int brow = nw * 32 + (lane >> 4) * 8 + (lane & 7);
            const int bcol = kk + ((lane >> 3) & 1) * 8;
            #pragma unroll
            for (int jj = 0; jj < 2; jj++) {
                const uint32_t o = SW((brow + jj * 16) * 128 + bcol * 2);
                uint32_t t[4];
                ldsm4(khi_a + o, t);
                bh2[2 * jj][0] = t[0]; bh2[2 * jj][1] = t[1];
                bh2[2 * jj + 1][0] = t[2]; bh2[2 * jj + 1][1] = t[3];
                ldsm4(klo_a + o, t);
                bl[2 * jj][0] = t[0]; bl[2 * jj][1] = t[1];
                bl[2 * jj + 1][0] = t[2]; bl[2 * jj + 1][1] = t[3];
            }
            #pragma unroll
            for (int i = 0; i < 4; i++)
                #pragma unroll
                for (int j = 0; j < 4; j++) {
                    mma16816(acc[i][j], ah[i], bh2[j]);
                    mma16816(acc[i][j], ah[i], bl[j]);
                    mma16816(acc[i][j], al[i], bh2[j]);
                }
        }

        #pragma unroll
        for (int i = 0; i < 4; i++)
            #pragma unroll
            for (int hr = 0; hr < 2; hr++) {
                const int r = m0 + mw * 64 + i * 16 + group + hr * 8;
                const uint32_t bits = mb[i][hr];
                float zadd = 0.f;
                #pragma unroll
                for (int j = 0; j < 4; j++) {
                    const int c = n0 + nw * 32 + j * 8 + 2 * tig;
                    const int bpos = j * 8 + 2 * tig;
                    const float e0 = ((bits >> bpos) & 1u) ? 0.f : __expf(acc[i][j][2 * hr + 0]);
                    const float e1 = ((bits >> (bpos + 1)) & 1u) ? 0.f : __expf(acc[i][j][2 * hr + 1]);
                    const size_t so = ((size_t)bh * Ls + r) * Ls + c;
                    *(__half2*)(g_pe + so) = __floats2half2_rn(e0, e1);
                    zadd += e0 + e1;
                }
                zloc[i][hr] += zadd;
            }
        __syncthreads();
    }

    #pragma unroll
    for (int i = 0; i < 4; i++)
        #pragma unroll
        for (int hr = 0; hr < 2; hr++) {
            float z = zloc[i][hr];
            z += __shfl_xor_sync(0xFFFFFFFFu, z, 1);
            z += __shfl_xor_sync(0xFFFFFFFFu, z, 2);
            if (tig == 0) {
                const int rloc = mw * 64 + i * 16 + hr * 8 + group;
                red_z[nw * 128 + rloc] = z;
            }
        }
    __syncthreads();
    if (tid < 128) {
        float z = red_z[tid] + red_z[128 + tid] + red_z[256 + tid] + red_z[384 + tid];
        g_iz[(size_t)bh * Ls + m0 + tid] = 1.f / z;
    }
}

// =====================================================================================
// avg: attn_avg[b,q,k] = qmask/Hh * sum_h e*iz_h.  Read-only fp16 stream.
// =====================================================================================
__global__ void __launch_bounds__(256) avg_kernel(const float* __restrict__ qmask,
                                                  float* __restrict__ avg_out)
{
    const int tid = threadIdx.x;
    const int tx = tid & 15, ty = tid >> 4;
    const int k0 = blockIdx.x * 64;
    const int q0 = blockIdx.y * 64;
    const int b = blockIdx.z;

    float sum[4][4] = {};
    for (int h = 0; h < Hh; h++) {
        const int bhh = b * Hh + h;
        #pragma unroll
        for (int i = 0; i < 4; i++) {
            const int q = q0 + ty * 4 + i;
            const float iz = g_iz[(size_t)bhh * Ls + q];
            const size_t so = ((size_t)bhh * Ls + q) * Ls + k0 + tx * 4;
            const __half2 e01 = *(const __half2*)(g_pe + so);
            const __half2 e23 = *(const __half2*)(g_pe + so + 2);
            const float2 f01 = __half22float2(e01);
            const float2 f23 = __half22float2(e23);
            sum[i][0] = fmaf(f01.x, iz, sum[i][0]);
            sum[i][1] = fmaf(f01.y, iz, sum[i][1]);
            sum[i][2] = fmaf(f23.x, iz, sum[i][2]);
            sum[i][3] = fmaf(f23.y, iz, sum[i][3]);
        }
    }
    #pragma unroll
    for (int i = 0; i < 4; i++) {
        const int q = q0 + ty * 4 + i;
        const float qm = qmask[b * Ls + q] * (1.f / (float)Hh);
        float4 o;
        o.x = sum[i][0] * qm; o.y = sum[i][1] * qm; o.z = sum[i][2] * qm; o.w = sum[i][3] * qm;
        *(float4*)(avg_out + (size_t)(b * Ls + q) * Ls + k0 + tx * 4) = o;
    }
}

// =====================================================================================
// PV: C[128,64] = (E[128,2048] @ V^T) * iz. E single fp16, V fp16 hi/lo transposed.
// k-chunk 64 (stride-72 smem, conflict-free) -> 32 stage iterations instead of 64.
// Dyn smem: 2 stages x (P 128*72 + 2*V 64*72) halves = 73728 B (2 CTA/SM).
// =====================================================================================
__global__ void __launch_bounds__(256, 2) pv_kernel()
{
    extern __shared__ char smraw[];
    __half* sb = (__half*)smraw;
    const int PT = 128 * STR2;   // 9216
    const int VT = 64 * STR2;    // 4608
    const int STG = PT + 2 * VT; // 18432 halves per stage

    const int tid = threadIdx.x, wid = tid >> 5, lane = tid & 31;
    const int mw = wid >> 1, nw = wid & 1;
    const int m0 = blockIdx.x * 128;
    const int bh = blockIdx.y;
    const int b = bh >> 4, h = bh & 15;
    const int group = lane >> 2, tig = lane & 3;
    const __half* Pe  = g_pe  + (size_t)bh * Ls * Ls;
    const __half* Vhi = g_vhi + (size_t)bh * DPH * Ls;
    const __half* Vlo = g_vlo + (size_t)bh * DPH * Ls;

    auto stage_load = [&](int s, int t0) {
        __half* base = sb + s * STG;
        #pragma unroll
        for (int i = 0; i < 4; i++) {
            const int lin = tid + i * 256;
            const int r = lin >> 3, c = lin & 7;
            cpasync16(base + r * STR2 + c * 8, Pe + (size_t)(m0 + r) * Ls + t0 + c * 8);
        }
        #pragma unroll
        for (int i = 0; i < 2; i++) {
            const int lin = tid + i * 256;
            const int r = lin >> 3, c = lin & 7;
            cpasync16(base + PT + r * STR2 + c * 8,      Vhi + (size_t)r * Ls + t0 + c * 8);
            cpasync16(base + PT + VT + r * STR2 + c * 8, Vlo + (size_t)r * Ls + t0 + c * 8);
        }
        CP_COMMIT();
    };
    stage_load(0, 0);

    float acc[2][4][4] = {};

    for (int kc = 0; kc < Ls / 64; kc++) {
        if (kc < Ls / 64 - 1) { stage_load((kc + 1) & 1, (kc + 1) * 64); CP_WAIT1(); }
        else CP_WAIT0();
        __syncthreads();
        __half* base = sb + (kc & 1) * STG;
        __half* sPe  = base;
        __half* sVhi = base + PT;
        __half* sVlo = base + PT + VT;
        #pragma unroll
        for (int kk = 0; kk < 64; kk += 16) {
            uint32_t ah[2][4], bh2[4][2], bl[4][2];
            const int arow = mw * 32 + ((lane >> 3) & 1) * 8 + (lane & 7);
            const int acol = kk + (lane >> 4) * 8;
            #pragma unroll
            for (int i = 0; i < 2; i++)
                ldsm4(saddr(sPe + (arow + i * 16) * STR2 + acol), ah[i]);
            const int brow = nw * 32 + (lane >> 4) * 8 + (lane & 7);
            const int bcol = kk + ((lane >> 3) & 1) * 8;
            #pragma unroll
            for (int jj = 0; jj < 2; jj++) {
                uint32_t t[4];
                ldsm4(saddr(sVhi + (brow + jj * 16) * STR2 + bcol), t);
                bh2[2 * jj][0] = t[0]; bh2[2 * jj][1] = t[1];
                bh2[2 * jj + 1][0] = t[2]; bh2[2 * jj + 1][1] = t[3];
                ldsm4(saddr(sVlo + (brow + jj * 16) * STR2 + bcol), t);
                bl[2 * jj][0] = t[0]; bl[2 * jj][1] = t[1];
                bl[2 * jj + 1][0] = t[2]; bl[2 * jj + 1][1] = t[3];
            }
            #pragma unroll
            for (int i = 0; i < 2; i++)
                #pragma unroll
                for (int j = 0; j < 4; j++) {
                    mma16816h(acc[i][j], ah[i], bh2[j]);
                    mma16816h(acc[i][j], ah[i], bl[j]);
                }
        }
        __syncthreads();
    }

    float izv[2][2];
    #pragma unroll
    for (int i = 0; i < 2; i++)
        #pragma unroll
        for (int hr = 0; hr < 2; hr++) {
            const int r = m0 + mw * 32 + i * 16 + group + hr * 8;
            izv[i][hr] = g_iz[(size_t)bh * Ls + r];
        }

    #pragma unroll
    for (int i = 0; i < 2; i++)
        #pragma unroll
        for (int j = 0; j < 4; j++) {
            const int c = nw * 32 + j * 8 + 2 * tig;
            #pragma unroll
            for (int hr = 0; hr < 2; hr++) {
                const int r = m0 + mw * 32 + i * 16 + group + hr * 8;
                const size_t idx = (size_t)(b * Ls + r) * Dm + h * 64 + c;
                __nv_bfloat16 h0, h1, l0, l1;
                split1(acc[i][j][2 * hr + 0] * izv[i][hr], h0, l0);
                split1(acc[i][j][2 * hr + 1] * izv[i][hr], h1, l1);
                __nv_bfloat162 ph; ph.x = h0; ph.y = h1;
                __nv_bfloat162 pl; pl.x = l0; pl.y = l1;
                *(__nv_bfloat162*)(g_chi + idx) = ph;
                *(__nv_bfloat162*)(g_clo + idx) = pl;
            }
        }
}

// =====================================================================================
// Launch. Inputs: k, v, q, attn_mask, query_mask, kqv_w, kqv_b, fin_w, fin_b
// Side stream overlaps v-proj with qk and avg with pv (event fork/join, capture-safe).
// =====================================================================================
extern "C" void kernel_launch(void* const* d_in, const int* in_sizes, int n_in,
                              void* d_out, int out_size)
{
    (void)in_sizes; (void)n_in; (void)out_size;
    const float* k_in  = (const float*)d_in[0];
    const float* v_in  = (const float*)d_in[1];
    const float* q_in  = (const float*)d_in[2];
    const int*   amask = (const int*)  d_in[3];
    const float* qmask = (const float*)d_in[4];
    const float* kqv_w = (const float*)d_in[5];
    const float* kqv_b = (const float*)d_in[6];
    const float* fin_w = (const float*)d_in[7];
    const float* fin_b = (const float*)d_in[8];
    float* out_ctx = (float*)d_out;
    float* out_avg = out_ctx + (size_t)Bb * Ls * Dm;

    __nv_bfloat16 *xhi, *xlo, *whi, *wlo, *qhi, *qlo, *khi, *klo, *chi, *clo;
    __half *vhi, *vlo;
    cudaGetSymbolAddress((void**)&xhi, g_xhi); cudaGetSymbolAddress((void**)&xlo, g_xlo);
    cudaGetSymbolAddress((void**)&whi, g_whi); cudaGetSymbolAddress((void**)&wlo, g_wlo);
    cudaGetSymbolAddress((void**)&qhi, g_qhi); cudaGetSymbolAddress((void**)&qlo, g_qlo);
    cudaGetSymbolAddress((void**)&khi, g_khi); cudaGetSymbolAddress((void**)&klo, g_klo);
    cudaGetSymbolAddress((void**)&vhi, g_vhi); cudaGetSymbolAddress((void**)&vlo, g_vlo);
    cudaGetSymbolAddress((void**)&chi, g_chi); cudaGetSymbolAddress((void**)&clo, g_clo);

    const int GSM  = 2 * 4 * 128 * STR * 2;                  // 81920 B
    const int QKSM = 98304 + 4 * 128 * 4;                    // 100352 B
    const int PVSM = 2 * (128 * STR2 + 2 * 64 * STR2) * 2;   // 73728 B
    static int attr_set = 0;
    static cudaStream_t s2 = nullptr;
    static cudaEvent_t evFork = nullptr, evV = nullptr, evQK = nullptr, evAvg = nullptr;
    if (!attr_set) {
        cudaFuncSetAttribute(gemm_bf<0>, cudaFuncAttributeMaxDynamicSharedMemorySize, GSM);
        cudaFuncSetAttribute(gemm_bf<1>, cudaFuncAttributeMaxDynamicSharedMemorySize, GSM);
        cudaFuncSetAttribute(gemm_bf<2>, cudaFuncAttributeMaxDynamicSharedMemorySize, GSM);
        cudaFuncSetAttribute(qk_kernel,  cudaFuncAttributeMaxDynamicSharedMemorySize, QKSM);
        cudaFuncSetAttribute(pv_kernel,  cudaFuncAttributeMaxDynamicSharedMemorySize, PVSM);
        cudaStreamCreateWithFlags(&s2, cudaStreamNonBlocking);
        cudaEventCreateWithFlags(&evFork, cudaEventDisableTiming);
        cudaEventCreateWithFlags(&evV,    cudaEventDisableTiming);
        cudaEventCreateWithFlags(&evQK,   cudaEventDisableTiming);
        cudaEventCreateWithFlags(&evAvg,  cudaEventDisableTiming);
        attr_set = 1;
    }

    // --- prologue: split inputs/weights, pack mask (main stream) ---
    const int NIN = 8388608;
    convsplit<<<NIN / 1024, 256>>>(k_in, xhi,           xlo);
    convsplit<<<NIN / 1024, 256>>>(v_in, xhi + NIN,     xlo + NIN);
    convsplit<<<NIN / 1024, 256>>>(q_in, xhi + 2 * NIN, xlo + 2 * NIN);
    convsplit<<<(3 * 1048576) / 1024, 256>>>(kqv_w, whi,              wlo);
    convsplit<<<1048576 / 1024, 256>>>(fin_w, whi + 3 * 1048576, wlo + 3 * 1048576);
    packmask<<<(Bb * Ls * Ls / 32) / 256, 256>>>(amask);

    dim3 gg(Dm / 128, (Bb * Ls) / 128);    // (8, 64)
    // K and Q projections on main stream
    gemm_bf<0><<<gg, 256, GSM>>>(xhi, xlo, whi, wlo, kqv_b, nullptr, 1.0f, khi, klo, nullptr);
    gemm_bf<0><<<gg, 256, GSM>>>(xhi + 2 * NIN, xlo + 2 * NIN, whi + 1048576, wlo + 1048576,
                                 kqv_b + Dm, nullptr, 0.125f, qhi, qlo, nullptr);

    // fork: V projection on side stream (overlaps with qk)
    cudaEventRecord(evFork, 0);
    cudaStreamWaitEvent(s2, evFork, 0);
    gemm_bf<1><<<gg, 256, GSM, s2>>>(xhi + NIN, xlo + NIN, whi + 2 * 1048576, wlo + 2 * 1048576,
                                     kqv_b + 2 * Dm, nullptr, 1.0f, vhi, vlo, nullptr);
    cudaEventRecord(evV, s2);

    qk_kernel<<<dim3(Ls / 128, Bb * Hh), 256, QKSM>>>();
    cudaEventRecord(evQK, 0);

    // avg on side stream (overlaps with pv); depends on qk only
    cudaStreamWaitEvent(s2, evQK, 0);
    avg_kernel<<<dim3(Ls / 64, Ls / 64, Bb), 256, 0, s2>>>(qmask, out_avg);
    cudaEventRecord(evAvg, s2);

    // pv needs v-proj
    cudaStreamWaitEvent(0, evV, 0);
    pv_kernel<<<dim3(Ls / 128, Bb * Hh), 256, PVSM>>>();

    gemm_bf<2><<<gg, 256, GSM>>>(chi, clo, whi + 3 * 1048576, wlo + 3 * 1048576,
                                 fin_b, qmask, 1.0f, nullptr, nullptr, out_ctx);

    // join side stream back before capture ends
    cudaStreamWaitEvent(0, evAvg, 0);
}

// round 13
// speedup vs baseline: 1.1995x; 1.0749x over previous
#include <cuda_runtime.h>
#include <cuda_bf16.h>
#include <cuda_fp16.h>
#include <cstdint>
#include <math.h>

#define Bb   4
#define Ls   2048
#define Dm   1024
#define Hh   16
#define DPH  64
#define STR  40     // padded row stride (elems) for 32-col 16-bit tiles
#define STR2 72     // padded row stride for 64-col tiles (pv)

// ---------------- scratch (__device__ globals; allocation is forbidden) ----------------
__device__ __half g_pe[268435456];                 // e = exp(S) fp16 (512 MB), [bh][q][k]
__device__ __nv_bfloat16 g_xhi[3 * 8388608];       // inputs k,v,q split hi
__device__ __nv_bfloat16 g_xlo[3 * 8388608];
__device__ __nv_bfloat16 g_whi[4 * 1048576];       // kqv_w (3M) + fin_w (1M) hi
__device__ __nv_bfloat16 g_wlo[4 * 1048576];
__device__ __nv_bfloat16 g_qhi[8388608], g_qlo[8388608];   // q proj head-major [bh][l][d]
__device__ __nv_bfloat16 g_khi[8388608], g_klo[8388608];   // k proj head-major
__device__ __half g_vhi[8388608], g_vlo[8388608];          // v proj TRANSPOSED [bh][d][l], fp16 hi/lo
__device__ __nv_bfloat16 g_chi[8388608], g_clo[8388608];   // ctx [m][1024]
__device__ float g_iz[Bb * Hh * Ls];               // 1 / sum(exp(s)) per row
__device__ uint32_t g_mbits[Bb * Ls * Ls / 32];    // bit-packed attn_mask (2 MB)

// ============================ PTX helpers (sm_80+, valid on compute_103) ============================
__device__ __forceinline__ uint32_t saddr(const void* p) {
    return (uint32_t)__cvta_generic_to_shared(p);
}
__device__ __forceinline__ void ldsm4(uint32_t addr, uint32_t* r) {
    asm volatile("ldmatrix.sync.aligned.m8n8.x4.shared.b16 {%0,%1,%2,%3}, [%4];"
        : "=r"(r[0]), "=r"(r[1]), "=r"(r[2]), "=r"(r[3]) : "r"(addr));
}
__device__ __forceinline__ void mma16816(float* c, const uint32_t* a, const uint32_t* b) {
    asm volatile(
        "mma.sync.aligned.m16n8k16.row.col.f32.bf16.bf16.f32 "
        "{%0,%1,%2,%3},{%4,%5,%6,%7},{%8,%9},{%0,%1,%2,%3};"
        : "+f"(c[0]), "+f"(c[1]), "+f"(c[2]), "+f"(c[3])
        : "r"(a[0]), "r"(a[1]), "r"(a[2]), "r"(a[3]), "r"(b[0]), "r"(b[1]));
}
__device__ __forceinline__ void mma16816h(float* c, const uint32_t* a, const uint32_t* b) {
    asm volatile(
        "mma.sync.aligned.m16n8k16.row.col.f32.f16.f16.f32 "
        "{%0,%1,%2,%3},{%4,%5,%6,%7},{%8,%9},{%0,%1,%2,%3};"
        : "+f"(c[0]), "+f"(c[1]), "+f"(c[2]), "+f"(c[3])
        : "r"(a[0]), "r"(a[1]), "r"(a[2]), "r"(a[3]), "r"(b[0]), "r"(b[1]));
}
__device__ __forceinline__ void cpasync16(void* smem, const void* gmem) {
    asm volatile("cp.async.cg.shared.global [%0], [%1], 16;"
        :: "r"(saddr(smem)), "l"(gmem));
}
#define CP_COMMIT() asm volatile("cp.async.commit_group;")
#define CP_WAIT2()  asm volatile("cp.async.wait_group 2;")
#define CP_WAIT1()  asm volatile("cp.async.wait_group 1;")
#define CP_WAIT0()  asm volatile("cp.async.wait_group 0;")
#define SW(x) ((x) ^ (((x) >> 3) & 0x70))

__device__ __forceinline__ void split1(float v, __nv_bfloat16& h, __nv_bfloat16& l) {
    h = __float2bfloat16_rn(v);
    l = __float2bfloat16_rn(v - __bfloat162float(h));
}
__device__ __forceinline__ void split1h(float v, __half& h, __half& l) {
    h = __float2half_rn(v);
    l = __float2half_rn(v - __half2float(h));
}

// =====================================================================================
// fp32 -> bf16 hi/lo split for the 3 input tensors in one launch (blockIdx.y selects).
// =====================================================================================
__global__ void __launch_bounds__(256) convsplit3(const float* __restrict__ s0,
                                                  const float* __restrict__ s1,
                                                  const float* __restrict__ s2,
                                                  __nv_bfloat16* __restrict__ hi,
                                                  __nv_bfloat16* __restrict__ lo)
{
    const int t = blockIdx.y;
    const float* src = (t == 0) ? s0 : (t == 1) ? s1 : s2;
    const size_t base = (size_t)t * 8388608;
    const size_t i4 = ((size_t)blockIdx.x * 256 + threadIdx.x) * 4;
    float4 v = *(const float4*)(src + i4);
    __nv_bfloat16 h0, h1, h2, h3, l0, l1, l2, l3;
    split1(v.x, h0, l0); split1(v.y, h1, l1); split1(v.z, h2, l2); split1(v.w, h3, l3);
    __nv_bfloat162 a, b;
    a.x = h0; a.y = h1; b.x = h2; b.y = h3;
    *(__nv_bfloat162*)(hi + base + i4) = a; *(__nv_bfloat162*)(hi + base + i4 + 2) = b;
    a.x = l0; a.y = l1; b.x = l2; b.y = l3;
    *(__nv_bfloat162*)(lo + base + i4) = a; *(__nv_bfloat162*)(lo + base + i4 + 2) = b;
}

__global__ void __launch_bounds__(256) convsplit(const float* __restrict__ src,
                                                 __nv_bfloat16* __restrict__ hi,
                                                 __nv_bfloat16* __restrict__ lo)
{
    const size_t i4 = ((size_t)blockIdx.x * 256 + threadIdx.x) * 4;
    float4 v = *(const float4*)(src + i4);
    __nv_bfloat16 h0, h1, h2, h3, l0, l1, l2, l3;
    split1(v.x, h0, l0); split1(v.y, h1, l1); split1(v.z, h2, l2); split1(v.w, h3, l3);
    __nv_bfloat162 a, b;
    a.x = h0; a.y = h1; b.x = h2; b.y = h3;
    *(__nv_bfloat162*)(hi + i4) = a; *(__nv_bfloat162*)(hi + i4 + 2) = b;
    a.x = l0; a.y = l1; b.x = l2; b.y = l3;
    *(__nv_bfloat162*)(lo + i4) = a; *(__nv_bfloat162*)(lo + i4 + 2) = b;
}

// =====================================================================================
// Pack attn_mask int32 -> bits.
// =====================================================================================
__global__ void __launch_bounds__(256) packmask(const int* __restrict__ mask)
{
    const size_t w = (size_t)blockIdx.x * 256 + threadIdx.x;
    const int* p = mask + w * 32;
    uint32_t v = 0;
    #pragma unroll
    for (int i = 0; i < 8; i++) {
        int4 m = *(const int4*)(p + 4 * i);
        v |= (uint32_t)(m.x != 0) << (4 * i);
        v |= (uint32_t)(m.y != 0) << (4 * i + 1);
        v |= (uint32_t)(m.z != 0) << (4 * i + 2);
        v |= (uint32_t)(m.w != 0) << (4 * i + 3);
    }
    g_mbits[w] = v;
}

// =====================================================================================
// GEMM 128x128: C = X @ W^T (+bias). Single-sync double-buffered pipeline.
// EPI 0: q/k proj -> head-major bf16 hi/lo, *scale.
// EPI 1: v proj  -> transposed [bh][d][l] fp16 hi/lo.
// EPI 2: final   -> fp32 out [m][1024] * qmask.
// =====================================================================================
template <int EPI>
__global__ void __launch_bounds__(256, 2) gemm_bf(const __nv_bfloat16* __restrict__ Xhi,
                                                  const __nv_bfloat16* __restrict__ Xlo,
                                                  const __nv_bfloat16* __restrict__ Whi,
                                                  const __nv_bfloat16* __restrict__ Wlo,
                                                  const float* __restrict__ bias,
                                                  const float* __restrict__ qmask,
                                                  float scale,
                                                  void* __restrict__ Yhi_,
                                                  void* __restrict__ Ylo_,
                                                  float* __restrict__ Yf)
{
    extern __shared__ char smraw[];
    __nv_bfloat16* sb = (__nv_bfloat16*)smraw;
    const int TILE_E = 128 * STR;

    const int tid = threadIdx.x, wid = tid >> 5, lane = tid & 31;
    const int mw = wid >> 2, nw = wid & 3;
    const int m0 = blockIdx.y * 128, n0 = blockIdx.x * 128;
    const int group = lane >> 2, tig = lane & 3;

    float acc[4][4][4] = {};

    auto stage_load = [&](int s, int k0) {
        __nv_bfloat16* base = sb + s * 4 * TILE_E;
        #pragma unroll
        for (int i = 0; i < 4; i++) {
            const int lin = tid + i * 256;
            const int r = lin >> 3, c = lin & 7;
            if (c < 4) {
                cpasync16(base + r * STR + c * 8,             Xhi + (size_t)(m0 + r) * Dm + k0 + c * 8);
                cpasync16(base + TILE_E + r * STR + c * 8,    Xlo + (size_t)(m0 + r) * Dm + k0 + c * 8);
            } else {
                const int cc = c - 4;
                cpasync16(base + 2 * TILE_E + r * STR + cc * 8, Whi + (size_t)(n0 + r) * Dm + k0 + cc * 8);
                cpasync16(base + 3 * TILE_E + r * STR + cc * 8, Wlo + (size_t)(n0 + r) * Dm + k0 + cc * 8);
            }
        }
        CP_COMMIT();
    };

    stage_load(0, 0);

    for (int kc = 0; kc < 32; kc++) {
        CP_WAIT0();
        __syncthreads();
        if (kc < 31) stage_load((kc + 1) & 1, (kc + 1) * 32);
        __nv_bfloat16* base = sb + (kc & 1) * 4 * TILE_E;
        __nv_bfloat16* sXhi = base;
        __nv_bfloat16* sXlo = base + TILE_E;
        __nv_bfloat16* sWhi = base + 2 * TILE_E;
        __nv_bfloat16* sWlo = base + 3 * TILE_E;
        #pragma unroll
        for (int kk = 0; kk < 32; kk += 16) {
            uint32_t ah[4][4], al[4][4], bh[4][2], bl[4][2];
            const int arow = mw * 64 + ((lane >> 3) & 1) * 8 + (lane & 7);
            const int acol = kk + (lane >> 4) * 8;
            #pragma unroll
            for (int i = 0; i < 4; i++) {
                ldsm4(saddr(sXhi + (arow + i * 16) * STR + acol), ah[i]);
                ldsm4(saddr(sXlo + (arow + i * 16) * STR + acol), al[i]);
            }
            const int brow = nw * 32 + (lane >> 4) * 8 + (lane & 7);
            const int bcol = kk + ((lane >> 3) & 1) * 8;
            #pragma unroll
            for (int jj = 0; jj < 2; jj++) {
                uint32_t t[4];
                ldsm4(saddr(sWhi + (brow + jj * 16) * STR + bcol), t);
                bh[2 * jj][0] = t[0]; bh[2 * jj][1] = t[1];
                bh[2 * jj + 1][0] = t[2]; bh[2 * jj + 1][1] = t[3];
                ldsm4(saddr(sWlo + (brow + jj * 16) * STR + bcol), t);
                bl[2 * jj][0] = t[0]; bl[2 * jj][1] = t[1];
                bl[2 * jj + 1][0] = t[2]; bl[2 * jj + 1][1] = t[3];
            }
            #pragma unroll
            for (int i = 0; i < 4; i++)
                #pragma unroll
                for (int j = 0; j < 4; j++) {
                    mma16816(acc[i][j], ah[i], bh[j]);
                    mma16816(acc[i][j], ah[i], bl[j]);
                    mma16816(acc[i][j], al[i], bh[j]);
                }
        }
    }

    #pragma unroll
    for (int i = 0; i < 4; i++)
        #pragma unroll
        for (int j = 0; j < 4; j++) {
            const int c = n0 + nw * 32 + j * 8 + 2 * tig;
            const float2 bv = *(const float2*)(bias + c);
            #pragma unroll
            for (int hr = 0; hr < 2; hr++) {
                const int r = m0 + mw * 64 + i * 16 + group + hr * 8;
                const float o0 = (acc[i][j][2 * hr + 0] + bv.x) * (EPI == 2 ? qmask[r] : scale);
                const float o1 = (acc[i][j][2 * hr + 1] + bv.y) * (EPI == 2 ? qmask[r] : scale);
                if (EPI == 2) {
                    *(float2*)(Yf + (size_t)r * Dm + c) = make_float2(o0, o1);
                } else if (EPI == 0) {
                    const int h = c >> 6, d = c & 63;
                    const int bb = r >> 11, l = r & (Ls - 1);
                    __nv_bfloat16 h0, h1, l0, l1;
                    split1(o0, h0, l0); split1(o1, h1, l1);
                    const size_t idx = ((size_t)(bb * Hh + h) * Ls + l) * DPH + d;
                    __nv_bfloat162 ph; ph.x = h0; ph.y = h1;
                    __nv_bfloat162 pl; pl.x = l0; pl.y = l1;
                    *(__nv_bfloat162*)((__nv_bfloat16*)Yhi_ + idx) = ph;
                    *(__nv_bfloat162*)((__nv_bfloat16*)Ylo_ + idx) = pl;
                } else {
                    const int h = c >> 6, d = c & 63;
                    const int bb = r >> 11, l = r & (Ls - 1);
                    __half h0, h1, l0, l1;
                    split1h(o0, h0, l0); split1h(o1, h1, l1);
                    const size_t idx = ((size_t)(bb * Hh + h) * DPH + d) * Ls + l;
                    ((__half*)Yhi_)[idx] = h0; ((__half*)Ylo_)[idx] = l0;
                    ((__half*)Yhi_)[idx + Ls] = h1; ((__half*)Ylo_)[idx + Ls] = l1;
                }
            }
        }
}

// =====================================================================================
// Fused QK + exp + z. Single-sync double-buffered K pipeline.
// =====================================================================================
__global__ void __launch_bounds__(256, 2) qk_kernel()
{
    extern __shared__ char smraw[];
    char* sQhi = smraw;
    char* sQlo = smraw + 16384;
    char* sK   = smraw + 32768;                     // [stage][hi 16384 | lo 16384]
    float* red_z = (float*)(smraw + 98304);

    const int tid = threadIdx.x, wid = tid >> 5, lane = tid & 31;
    const int mw = wid >> 2, nw = wid & 3;
    const int m0 = blockIdx.x * 128;
    const int bh = blockIdx.y;
    const int b = bh >> 4;
    const int group = lane >> 2, tig = lane & 3;
    const __nv_bfloat16* Qhi = g_qhi + (size_t)bh * Ls * DPH;
    const __nv_bfloat16* Qlo = g_qlo + (size_t)bh * Ls * DPH;
    const __nv_bfloat16* Khi = g_khi + (size_t)bh * Ls * DPH;
    const __nv_bfloat16* Klo = g_klo + (size_t)bh * Ls * DPH;

    #pragma unroll
    for (int i = 0; i < 4; i++) {
        const int lin = tid + i * 256;
        const int r = lin >> 3, ch = lin & 7;
        const uint32_t off = SW(r * 128 + ch * 16);
        cpasync16(sQhi + off, Qhi + (size_t)(m0 + r) * DPH + ch * 8);
        cpasync16(sQlo + off, Qlo + (size_t)(m0 + r) * DPH + ch * 8);
    }

    auto kload = [&](int s, int n0) {
        char* khb = sK + s * 32768;
        char* klb = khb + 16384;
        #pragma unroll
        for (int i = 0; i < 4; i++) {
            const int lin = tid + i * 256;
            const int r = lin >> 3, ch = lin & 7;
            const uint32_t off = SW(r * 128 + ch * 16);
            cpasync16(khb + off, Khi + (size_t)(n0 + r) * DPH + ch * 8);
            cpasync16(klb + off, Klo + (size_t)(n0 + r) * DPH + ch * 8);
        }
        CP_COMMIT();
    };
    kload(0, 0);      // commits Q loads + K tile 0 together

    float zloc[4][2] = {};
    const uint32_t qhi_a = saddr(sQhi), qlo_a = saddr(sQlo);

    for (int nt = 0; nt < Ls / 128; nt++) {
        const int n0 = nt * 128;
        CP_WAIT0();
        __syncthreads();
        if (nt < Ls / 128 - 1) kload((nt + 1) & 1, n0 + 128);

        uint32_t mb[4][2];
        #pragma unroll
        for (int i = 0; i < 4; i++)
            #pragma unroll
            for (int hr = 0; hr < 2; hr++) {
                const int r = m0 + mw * 64 + i * 16 + group + hr * 8;
                mb[i][hr] = g_mbits[(size_t)(b * Ls + r) * (Ls / 32) + ((n0 + nw * 32) >> 5)];
            }

        const uint32_t khi_a = saddr(sK + (nt & 1) * 32768);
        const uint32_t klo_a = khi_a + 16384;

        float acc[4][4][4] = {};
        #pragma unroll
        for (int kk = 0; kk < DPH; kk += 16) {
            uint32_t ah[4][4], al[4][4], bh2[4][2], bl[4][2];
            const int arow = mw * 64 + ((lane >> 3) & 1) * 8 + (lane & 7);
            const int acol = kk + (lane >> 4) * 8;
            #pragma unroll
            for (int i = 0; i < 4; i++) {
                const uint32_t o = SW((arow + i * 16) * 128 + acol * 2);
                ldsm4(qhi_a + o, ah[i]);
                ldsm4(qlo_a + o, al[i]);
            }
            const int brow = nw * 32 + (lane >> 4) * 8 + (lane & 7);
            const int bcol = kk + ((lane >> 3) & 1) * 8;
            #pragma unroll
            for (int jj = 0; jj < 2; jj++) {
                const uint32_t o = SW((brow + jj * 16) * 128 + bcol * 2);
                uint32_t t[4];
                ldsm4(khi_a + o, t);
                bh2[2 * jj][0] = t[0]; bh2[2 * jj][1] = t[1];
                bh2[2 * jj + 1][0] = t[2]; bh2[2 * jj + 1][1] = t[3];
                ldsm4(klo_a + o, t);
                bl[2 * jj][0] = t[0]; bl[2 * jj][1] = t[1];
                bl[2 * jj + 1][0] = t[2]; bl[2 * jj + 1][1] = t[3];
            }
            #pragma unroll
            for (int i = 0; i < 4; i++)
                #pragma unroll
                for (int j = 0; j < 4; j++) {
                    mma16816(acc[i][j], ah[i], bh2[j]);
                    mma16816(acc[i][j], ah[i], bl[j]);
                    mma16816(acc[i][j], al[i], bh2[j]);
                }
        }

        #pragma unroll
        for (int i = 0; i < 4; i++)
            #pragma unroll
            for (int hr = 0; hr < 2; hr++) {
                const int r = m0 + mw * 64 + i * 16 + group + hr * 8;
                const uint32_t bits = mb[i][hr];
                float zadd = 0.f;
                #pragma unroll
                for (int j = 0; j < 4; j++) {
                    const int c = n0 + nw * 32 + j * 8 + 2 * tig;
                    const int bpos = j * 8 + 2 * tig;
                    const float e0 = ((bits >> bpos) & 1u) ? 0.f : __expf(acc[i][j][2 * hr + 0]);
                    const float e1 = ((bits >> (bpos + 1)) & 1u) ? 0.f : __expf(acc[i][j][2 * hr + 1]);
                    const size_t so = ((size_t)bh * Ls + r) * Ls + c;
                    *(__half2*)(g_pe + so) = __floats2half2_rn(e0, e1);
                    zadd += e0 + e1;
                }
                zloc[i][hr] += zadd;
            }
    }

    #pragma unroll
    for (int i = 0; i < 4; i++)
        #pragma unroll
        for (int hr = 0; hr < 2; hr++) {
            float z = zloc[i][hr];
            z += __shfl_xor_sync(0xFFFFFFFFu, z, 1);
            z += __shfl_xor_sync(0xFFFFFFFFu, z, 2);
            if (tig == 0) {
                const int rloc = mw * 64 + i * 16 + hr * 8 + group;
                red_z[nw * 128 + rloc] = z;
            }
        }
    __syncthreads();
    if (tid < 128) {
        float z = red_z[tid] + red_z[128 + tid] + red_z[256 + tid] + red_z[384 + tid];
        g_iz[(size_t)bh * Ls + m0 + tid] = 1.f / z;
    }
}

// =====================================================================================
// avg: attn_avg[b,q,k] = qmask/Hh * sum_h e*iz_h.  Read-only fp16 stream.
// =====================================================================================
__global__ void __launch_bounds__(256) avg_kernel(const float* __restrict__ qmask,
                                                  float* __restrict__ avg_out)
{
    const int tid = threadIdx.x;
    const int tx = tid & 15, ty = tid >> 4;
    const int k0 = blockIdx.x * 64;
    const int q0 = blockIdx.y * 64;
    const int b = blockIdx.z;

    float sum[4][4] = {};
    for (int h = 0; h < Hh; h++) {
        const int bhh = b * Hh + h;
        #pragma unroll
        for (int i = 0; i < 4; i++) {
            const int q = q0 + ty * 4 + i;
            const float iz = g_iz[(size_t)bhh * Ls + q];
            const size_t so = ((size_t)bhh * Ls + q) * Ls + k0 + tx * 4;
            const __half2 e01 = *(const __half2*)(g_pe + so);
            const __half2 e23 = *(const __half2*)(g_pe + so + 2);
            const float2 f01 = __half22float2(e01);
            const float2 f23 = __half22float2(e23);
            sum[i][0] = fmaf(f01.x, iz, sum[i][0]);
            sum[i][1] = fmaf(f01.y, iz, sum[i][1]);
            sum[i][2] = fmaf(f23.x, iz, sum[i][2]);
            sum[i][3] = fmaf(f23.y, iz, sum[i][3]);
        }
    }
    #pragma unroll
    for (int i = 0; i < 4; i++) {
        const int q = q0 + ty * 4 + i;
        const float qm = qmask[b * Ls + q] * (1.f / (float)Hh);
        float4 o;
        o.x = sum[i][0] * qm; o.y = sum[i][1] * qm; o.z = sum[i][2] * qm; o.w = sum[i][3] * qm;
        *(float4*)(avg_out + (size_t)(b * Ls + q) * Ls + k0 + tx * 4) = o;
    }
}

// =====================================================================================
// PV: C[128,64] = (E[128,2048] @ V^T) * iz. 3-stage single-sync cp.async pipeline.
// Dyn smem: 3 stages x (P 128*72 + 2*V 64*72) halves x2B = 110592 B (2 CTA/SM).
// =====================================================================================
__global__ void __launch_bounds__(256, 2) pv_kernel()
{
    extern __shared__ char smraw[];
    __half* sb = (__half*)smraw;
    const int PT = 128 * STR2;   // 9216
    const int VT = 64 * STR2;    // 4608
    const int STG = PT + 2 * VT; // 18432 halves per stage
    const int NC = Ls / 64;      // 32 chunks

    const int tid = threadIdx.x, wid = tid >> 5, lane = tid & 31;
    const int mw = wid >> 1, nw = wid & 1;
    const int m0 = blockIdx.x * 128;
    const int bh = blockIdx.y;
    const int b = bh >> 4, h = bh & 15;
    const int group = lane >> 2, tig = lane & 3;
    const __half* Pe  = g_pe  + (size_t)bh * Ls * Ls;
    const __half* Vhi = g_vhi + (size_t)bh * DPH * Ls;
    const __half* Vlo = g_vlo + (size_t)bh * DPH * Ls;

    auto stage_load = [&](int s, int t0) {
        __half* base = sb + s * STG;
        #pragma unroll
        for (int i = 0; i < 4; i++) {
            const int lin = tid + i * 256;
            const int r = lin >> 3, c = lin & 7;
            cpasync16(base + r * STR2 + c * 8, Pe + (size_t)(m0 + r) * Ls + t0 + c * 8);
        }
        #pragma unroll
        for (int i = 0; i < 2; i++) {
            const int lin = tid + i * 256;
            const int r = lin >> 3, c = lin & 7;
            cpasync16(base + PT + r * STR2 + c * 8,      Vhi + (size_t)r * Ls + t0 + c * 8);
            cpasync16(base + PT + VT + r * STR2 + c * 8, Vlo + (size_t)r * Ls + t0 + c * 8);
        }
        CP_COMMIT();
    };
    stage_load(0, 0);
    stage_load(1, 64);

    float acc[2][4][4] = {};

    for (int kc = 0; kc < NC; kc++) {
        if (kc + 1 < NC) CP_WAIT1(); else CP_WAIT0();
        __syncthreads();
        if (kc + 2 < NC) stage_load((kc + 2) % 3, (kc + 2) * 64);
        __half* base = sb + (kc % 3) * STG;
        __half* sPe  = base;
        __half* sVhi = base + PT;
        __half* sVlo = base + PT + VT;
        #pragma unroll
        for (int kk = 0; kk < 64; kk += 16) {
            uint32_t ah[2][4], bh2[4][2], bl[4][2];
            const int arow = mw * 32 + ((lane >> 3) & 1) * 8 + (lane & 7);
            const int acol = kk + (lane >> 4) * 8;
            #pragma unroll
            for (int i = 0; i < 2; i++)
                ldsm4(saddr(sPe + (arow + i * 16) * STR2 + acol), ah[i]);
            const int brow = nw * 32 + (lane >> 4) * 8 + (lane & 7);
            const int bcol = kk + ((lane >> 3) & 1) * 8;
            #pragma unroll
            for (int jj = 0; jj < 2; jj++) {
                uint32_t t[4];
                ldsm4(saddr(sVhi + (brow + jj * 16) * STR2 + bcol), t);
                bh2[2 * jj][0] = t[0]; bh2[2 * jj][1] = t[1];
                bh2[2 * jj + 1][0] = t[2]; bh2[2 * jj + 1][1] = t[3];
                ldsm4(saddr(sVlo + (brow + jj * 16) * STR2 + bcol), t);
                bl[2 * jj][0] = t[0]; bl[2 * jj][1] = t[1];
                bl[2 * jj + 1][0] = t[2]; bl[2 * jj + 1][1] = t[3];
            }
            #pragma unroll
            for (int i = 0; i < 2; i++)
                #pragma unroll
                for (int j = 0; j < 4; j++) {
                    mma16816h(acc[i][j], ah[i], bh2[j]);
                    mma16816h(acc[i][j], ah[i], bl[j]);
                }
        }
    }

    float izv[2][2];
    #pragma unroll
    for (int i = 0; i < 2; i++)
        #pragma unroll
        for (int hr = 0; hr < 2; hr++) {
            const int r = m0 + mw * 32 + i * 16 + group + hr * 8;
            izv[i][hr] = g_iz[(size_t)bh * Ls + r];
        }

    #pragma unroll
    for (int i = 0; i < 2; i++)
        #pragma unroll
        for (int j = 0; j < 4; j++) {
            const int c = nw * 32 + j * 8 + 2 * tig;
            #pragma unroll
            for (int hr = 0; hr < 2; hr++) {
                const int r = m0 + mw * 32 + i * 16 + group + hr * 8;
                const size_t idx = (size_t)(b * Ls + r) * Dm + h * 64 + c;
                __nv_bfloat16 h0, h1, l0, l1;
                split1(acc[i][j][2 * hr + 0] * izv[i][hr], h0, l0);
                split1(acc[i][j][2 * hr + 1] * izv[i][hr], h1, l1);
                __nv_bfloat162 ph; ph.x = h0; ph.y = h1;
                __nv_bfloat162 pl; pl.x = l0; pl.y = l1;
                *(__nv_bfloat162*)(g_chi + idx) = ph;
                *(__nv_bfloat162*)(g_clo + idx) = pl;
            }
        }
}

// =====================================================================================
// Launch. Streams: main = kproj -> qk -> pv -> fin; s2 = qproj, avg; s3 = vproj.
// =====================================================================================
extern "C" void kernel_launch(void* const* d_in, const int* in_sizes, int n_in,
                              void* d_out, int out_size)
{
    (void)in_sizes; (void)n_in; (void)out_size;
    const float* k_in  = (const float*)d_in[0];
    const float* v_in  = (const float*)d_in[1];
    const float* q_in  = (const float*)d_in[2];
    const int*   amask = (const int*)  d_in[3];
    const float* qmask = (const float*)d_in[4];
    const float* kqv_w = (const float*)d_in[5];
    const float* kqv_b = (const float*)d_in[6];
    const float* fin_w = (const float*)d_in[7];
    const float* fin_b = (const float*)d_in[8];
    float* out_ctx = (float*)d_out;
    float* out_avg = out_ctx + (size_t)Bb * Ls * Dm;

    __nv_bfloat16 *xhi, *xlo, *whi, *wlo, *qhi, *qlo, *khi, *klo, *chi, *clo;
    __half *vhi, *vlo;
    cudaGetSymbolAddress((void**)&xhi, g_xhi); cudaGetSymbolAddress((void**)&xlo, g_xlo);
    cudaGetSymbolAddress((void**)&whi, g_whi); cudaGetSymbolAddress((void**)&wlo, g_wlo);
    cudaGetSymbolAddress((void**)&qhi, g_qhi); cudaGetSymbolAddress((void**)&qlo, g_qlo);
    cudaGetSymbolAddress((void**)&khi, g_khi); cudaGetSymbolAddress((void**)&klo, g_klo);
    cudaGetSymbolAddress((void**)&vhi, g_vhi); cudaGetSymbolAddress((void**)&vlo, g_vlo);
    cudaGetSymbolAddress((void**)&chi, g_chi); cudaGetSymbolAddress((void**)&clo, g_clo);

    const int GSM  = 2 * 4 * 128 * STR * 2;                  // 81920 B
    const int QKSM = 98304 + 4 * 128 * 4;                    // 100352 B
    const int PVSM = 3 * (128 * STR2 + 2 * 64 * STR2) * 2;   // 110592 B
    static int attr_set = 0;
    static cudaStream_t s2 = nullptr, s3 = nullptr;
    static cudaEvent_t evFork = nullptr, evV = nullptr, evQ = nullptr, evQK = nullptr, evAvg = nullptr;
    if (!attr_set) {
        cudaFuncSetAttribute(gemm_bf<0>, cudaFuncAttributeMaxDynamicSharedMemorySize, GSM);
        cudaFuncSetAttribute(gemm_bf<1>, cudaFuncAttributeMaxDynamicSharedMemorySize, GSM);
        cudaFuncSetAttribute(gemm_bf<2>, cudaFuncAttributeMaxDynamicSharedMemorySize, GSM);
        cudaFuncSetAttribute(qk_kernel,  cudaFuncAttributeMaxDynamicSharedMemorySize, QKSM);
        cudaFuncSetAttribute(pv_kernel,  cudaFuncAttributeMaxDynamicSharedMemorySize, PVSM);
        cudaStreamCreateWithFlags(&s2, cudaStreamNonBlocking);
        cudaStreamCreateWithFlags(&s3, cudaStreamNonBlocking);
        cudaEventCreateWithFlags(&evFork, cudaEventDisableTiming);
        cudaEventCreateWithFlags(&evV,    cudaEventDisableTiming);
        cudaEventCreateWithFlags(&evQ,    cudaEventDisableTiming);
        cudaEventCreateWithFlags(&evQK,   cudaEventDisableTiming);
        cudaEventCreateWithFlags(&evAvg,  cudaEventDisableTiming);
        attr_set = 1;
    }

    // --- prologue (main stream) ---
    const int NIN = 8388608;
    convsplit3<<<dim3(NIN / 1024, 3), 256>>>(k_in, v_in, q_in, xhi, xlo);
    convsplit<<<(3 * 1048576) / 1024, 256>>>(kqv_w, whi,              wlo);
    convsplit<<<1048576 / 1024, 256>>>(fin_w, whi + 3 * 1048576, wlo + 3 * 1048576);
    packmask<<<(Bb * Ls * Ls / 32) / 256, 256>>>(amask);

    dim3 gg(Dm / 128, (Bb * Ls) / 128);    // (8, 64)

    // fork: three projections run concurrently
    cudaEventRecord(evFork, 0);
    cudaStreamWaitEvent(s2, evFork, 0);
    cudaStreamWaitEvent(s3, evFork, 0);

    gemm_bf<0><<<gg, 256, GSM>>>(xhi, xlo, whi, wlo, kqv_b, nullptr, 1.0f, khi, klo, nullptr);
    gemm_bf<0><<<gg, 256, GSM, s2>>>(xhi + 2 * NIN, xlo + 2 * NIN, whi + 1048576, wlo + 1048576,
                                     kqv_b + Dm, nullptr, 0.125f, qhi, qlo, nullptr);
    cudaEventRecord(evQ, s2);
    gemm_bf<1><<<gg, 256, GSM, s3>>>(xhi + NIN, xlo + NIN, whi + 2 * 1048576, wlo + 2 * 1048576,
                                     kqv_b + 2 * Dm, nullptr, 1.0f, vhi, vlo, nullptr);
    cudaEventRecord(evV, s3);

    cudaStreamWaitEvent(0, evQ, 0);
    qk_kernel<<<dim3(Ls / 128, Bb * Hh), 256, QKSM>>>();
    cudaEventRecord(evQK, 0);

    // avg on s2 (overlaps pv); depends on qk only
    cudaStreamWaitEvent(s2, evQK, 0);
    avg_kernel<<<dim3(Ls / 64, Ls / 64, Bb), 256, 0, s2>>>(qmask, out_avg);
    cudaEventRecord(evAvg, s2);

    cudaStreamWaitEvent(0, evV, 0);
    pv_kernel<<<dim3(Ls / 128, Bb * Hh), 256, PVSM>>>();

    gemm_bf<2><<<gg, 256, GSM>>>(chi, clo, whi + 3 * 1048576, wlo + 3 * 1048576,
                                 fin_b, qmask, 1.0f, nullptr, nullptr, out_ctx);

    cudaStreamWaitEvent(0, evAvg, 0);
}

// round 16
// speedup vs baseline: 1.2369x; 1.0312x over previous
#include <cuda_runtime.h>
#include <cuda_bf16.h>
#include <cuda_fp16.h>
#include <cstdint>
#include <math.h>

#define Bb   4
#define Ls   2048
#define Dm   1024
#define Hh   16
#define DPH  64
#define STR  40     // padded row stride (elems) for 32-col 16-bit tiles
#define STR2 72     // padded row stride for 64-col tiles (pv)

// ---------------- scratch (__device__ globals; allocation is forbidden) ----------------
__device__ __half g_pe[268435456];                 // e = exp(S) fp16 (512 MB), [bh][q][k]
__device__ __nv_bfloat16 g_xhi[3 * 8388608];       // inputs k,v,q split hi
__device__ __nv_bfloat16 g_xlo[3 * 8388608];
__device__ __nv_bfloat16 g_whi[4 * 1048576];       // kqv_w (3M) + fin_w (1M) hi
__device__ __nv_bfloat16 g_wlo[4 * 1048576];
__device__ __nv_bfloat16 g_qhi[8388608], g_qlo[8388608];   // q proj head-major [bh][l][d]
__device__ __nv_bfloat16 g_khi[8388608], g_klo[8388608];   // k proj head-major
__device__ __half g_vhi[8388608], g_vlo[8388608];          // v proj TRANSPOSED [bh][d][l], fp16 hi/lo
__device__ __nv_bfloat16 g_chi[8388608], g_clo[8388608];   // ctx [m][1024]
__device__ float g_iz[Bb * Hh * Ls];               // 1 / sum(exp(s)) per row
__device__ uint32_t g_mbits[Bb * Ls * Ls / 32];    // bit-packed attn_mask (2 MB)

// ============================ PTX helpers (sm_80+, valid on compute_103) ============================
__device__ __forceinline__ uint32_t saddr(const void* p) {
    return (uint32_t)__cvta_generic_to_shared(p);
}
__device__ __forceinline__ void ldsm4(uint32_t addr, uint32_t* r) {
    asm volatile("ldmatrix.sync.aligned.m8n8.x4.shared.b16 {%0,%1,%2,%3}, [%4];"
        : "=r"(r[0]), "=r"(r[1]), "=r"(r[2]), "=r"(r[3]) : "r"(addr));
}
__device__ __forceinline__ void mma16816(float* c, const uint32_t* a, const uint32_t* b) {
    asm volatile(
        "mma.sync.aligned.m16n8k16.row.col.f32.bf16.bf16.f32 "
        "{%0,%1,%2,%3},{%4,%5,%6,%7},{%8,%9},{%0,%1,%2,%3};"
        : "+f"(c[0]), "+f"(c[1]), "+f"(c[2]), "+f"(c[3])
        : "r"(a[0]), "r"(a[1]), "r"(a[2]), "r"(a[3]), "r"(b[0]), "r"(b[1]));
}
__device__ __forceinline__ void mma16816h(float* c, const uint32_t* a, const uint32_t* b) {
    asm volatile(
        "mma.sync.aligned.m16n8k16.row.col.f32.f16.f16.f32 "
        "{%0,%1,%2,%3},{%4,%5,%6,%7},{%8,%9},{%0,%1,%2,%3};"
        : "+f"(c[0]), "+f"(c[1]), "+f"(c[2]), "+f"(c[3])
        : "r"(a[0]), "r"(a[1]), "r"(a[2]), "r"(a[3]), "r"(b[0]), "r"(b[1]));
}
__device__ __forceinline__ void cpasync16(void* smem, const void* gmem) {
    asm volatile("cp.async.cg.shared.global [%0], [%1], 16;"
        :: "r"(saddr(smem)), "l"(gmem));
}
#define CP_COMMIT() asm volatile("cp.async.commit_group;")
#define CP_WAIT1()  asm volatile("cp.async.wait_group 1;")
#define CP_WAIT0()  asm volatile("cp.async.wait_group 0;")
#define SW(x) ((x) ^ (((x) >> 3) & 0x70))

__device__ __forceinline__ void split1(float v, __nv_bfloat16& h, __nv_bfloat16& l) {
    h = __float2bfloat16_rn(v);
    l = __float2bfloat16_rn(v - __bfloat162float(h));
}
__device__ __forceinline__ void split1h(float v, __half& h, __half& l) {
    h = __float2half_rn(v);
    l = __float2half_rn(v - __half2float(h));
}

// =====================================================================================
// fp32 -> bf16 hi/lo split for the 3 input tensors in one launch (blockIdx.y selects).
// =====================================================================================
__global__ void __launch_bounds__(256) convsplit3(const float* __restrict__ s0,
                                                  const float* __restrict__ s1,
                                                  const float* __restrict__ s2,
                                                  __nv_bfloat16* __restrict__ hi,
                                                  __nv_bfloat16* __restrict__ lo)
{
    const int t = blockIdx.y;
    const float* src = (t == 0) ? s0 : (t == 1) ? s1 : s2;
    const size_t base = (size_t)t * 8388608;
    const size_t i4 = ((size_t)blockIdx.x * 256 + threadIdx.x) * 4;
    float4 v = *(const float4*)(src + i4);
    __nv_bfloat16 h0, h1, h2, h3, l0, l1, l2, l3;
    split1(v.x, h0, l0); split1(v.y, h1, l1); split1(v.z, h2, l2); split1(v.w, h3, l3);
    __nv_bfloat162 a, b;
    a.x = h0; a.y = h1; b.x = h2; b.y = h3;
    *(__nv_bfloat162*)(hi + base + i4) = a; *(__nv_bfloat162*)(hi + base + i4 + 2) = b;
    a.x = l0; a.y = l1; b.x = l2; b.y = l3;
    *(__nv_bfloat162*)(lo + base + i4) = a; *(__nv_bfloat162*)(lo + base + i4 + 2) = b;
}

__global__ void __launch_bounds__(256) convsplit(const float* __restrict__ src,
                                                 __nv_bfloat16* __restrict__ hi,
                                                 __nv_bfloat16* __restrict__ lo)
{
    const size_t i4 = ((size_t)blockIdx.x * 256 + threadIdx.x) * 4;
    float4 v = *(const float4*)(src + i4);
    __nv_bfloat16 h0, h1, h2, h3, l0, l1, l2, l3;
    split1(v.x, h0, l0); split1(v.y, h1, l1); split1(v.z, h2, l2); split1(v.w, h3, l3);
    __nv_bfloat162 a, b;
    a.x = h0; a.y = h1; b.x = h2; b.y = h3;
    *(__nv_bfloat162*)(hi + i4) = a; *(__nv_bfloat162*)(hi + i4 + 2) = b;
    a.x = l0; a.y = l1; b.x = l2; b.y = l3;
    *(__nv_bfloat162*)(lo + i4) = a; *(__nv_bfloat162*)(lo + i4 + 2) = b;
}

// =====================================================================================
// Pack attn_mask int32 -> bits.
// =====================================================================================
__global__ void __launch_bounds__(256) packmask(const int* __restrict__ mask)
{
    const size_t w = (size_t)blockIdx.x * 256 + threadIdx.x;
    const int* p = mask + w * 32;
    uint32_t v = 0;
    #pragma unroll
    for (int i = 0; i < 8; i++) {
        int4 m = *(const int4*)(p + 4 * i);
        v |= (uint32_t)(m.x != 0) << (4 * i);
        v |= (uint32_t)(m.y != 0) << (4 * i + 1);
        v |= (uint32_t)(m.z != 0) << (4 * i + 2);
        v |= (uint32_t)(m.w != 0) << (4 * i + 3);
    }
    g_mbits[w] = v;
}

// =====================================================================================
// GEMM 128x128: C = X @ W^T (+bias). Single-sync double-buffered pipeline.
// yoff: row-block offset (for per-batch fin launches).
// EPI 0: q/k proj -> head-major bf16 hi/lo, *scale.
// EPI 1: v proj  -> transposed [bh][d][l] fp16 hi/lo.
// EPI 2: final   -> fp32 out [m][1024] * qmask.
// =====================================================================================
template <int EPI>
__global__ void __launch_bounds__(256, 2) gemm_bf(const __nv_bfloat16* __restrict__ Xhi,
                                                  const __nv_bfloat16* __restrict__ Xlo,
                                                  const __nv_bfloat16* __restrict__ Whi,
                                                  const __nv_bfloat16* __restrict__ Wlo,
                                                  const float* __restrict__ bias,
                                                  const float* __restrict__ qmask,
                                                  float scale, int yoff,
                                                  void* __restrict__ Yhi_,
                                                  void* __restrict__ Ylo_,
                                                  float* __restrict__ Yf)
{
    extern __shared__ char smraw[];
    __nv_bfloat16* sb = (__nv_bfloat16*)smraw;
    const int TILE_E = 128 * STR;

    const int tid = threadIdx.x, wid = tid >> 5, lane = tid & 31;
    const int mw = wid >> 2, nw = wid & 3;
    const int m0 = (yoff + blockIdx.y) * 128, n0 = blockIdx.x * 128;
    const int group = lane >> 2, tig = lane & 3;

    float acc[4][4][4] = {};

    auto stage_load = [&](int s, int k0) {
        __nv_bfloat16* base = sb + s * 4 * TILE_E;
        #pragma unroll
        for (int i = 0; i < 4; i++) {
            const int lin = tid + i * 256;
            const int r = lin >> 3, c = lin & 7;
            if (c < 4) {
                cpasync16(base + r * STR + c * 8,             Xhi + (size_t)(m0 + r) * Dm + k0 + c * 8);
                cpasync16(base + TILE_E + r * STR + c * 8,    Xlo + (size_t)(m0 + r) * Dm + k0 + c * 8);
            } else {
                const int cc = c - 4;
                cpasync16(base + 2 * TILE_E + r * STR + cc * 8, Whi + (size_t)(n0 + r) * Dm + k0 + cc * 8);
                cpasync16(base + 3 * TILE_E + r * STR + cc * 8, Wlo + (size_t)(n0 + r) * Dm + k0 + cc * 8);
            }
        }
        CP_COMMIT();
    };

    stage_load(0, 0);

    for (int kc = 0; kc < 32; kc++) {
        CP_WAIT0();
        __syncthreads();
        if (kc < 31) stage_load((kc + 1) & 1, (kc + 1) * 32);
        __nv_bfloat16* base = sb + (kc & 1) * 4 * TILE_E;
        __nv_bfloat16* sXhi = base;
        __nv_bfloat16* sXlo = base + TILE_E;
        __nv_bfloat16* sWhi = base + 2 * TILE_E;
        __nv_bfloat16* sWlo = base + 3 * TILE_E;
        #pragma unroll
        for (int kk = 0; kk < 32; kk += 16) {
            uint32_t ah[4][4], al[4][4], bh[4][2], bl[4][2];
            const int arow = mw * 64 + ((lane >> 3) & 1) * 8 + (lane & 7);
            const int acol = kk + (lane >> 4) * 8;
            #pragma unroll
            for (int i = 0; i < 4; i++) {
                ldsm4(saddr(sXhi + (arow + i * 16) * STR + acol), ah[i]);
                ldsm4(saddr(sXlo + (arow + i * 16) * STR + acol), al[i]);
            }
            const int brow = nw * 32 + (lane >> 4) * 8 + (lane & 7);
            const int bcol = kk + ((lane >> 3) & 1) * 8;
            #pragma unroll
            for (int jj = 0; jj < 2; jj++) {
                uint32_t t[4];
                ldsm4(saddr(sWhi + (brow + jj * 16) * STR + bcol), t);
                bh[2 * jj][0] = t[0]; bh[2 * jj][1] = t[1];
                bh[2 * jj + 1][0] = t[2]; bh[2 * jj + 1][1] = t[3];
                ldsm4(saddr(sWlo + (brow + jj * 16) * STR + bcol), t);
                bl[2 * jj][0] = t[0]; bl[2 * jj][1] = t[1];
                bl[2 * jj + 1][0] = t[2]; bl[2 * jj + 1][1] = t[3];
            }
            #pragma unroll
            for (int i = 0; i < 4; i++)
                #pragma unroll
                for (int j = 0; j < 4; j++) {
                    mma16816(acc[i][j], ah[i], bh[j]);
                    mma16816(acc[i][j], ah[i], bl[j]);
                    mma16816(acc[i][j], al[i], bh[j]);
                }
        }
    }

    #pragma unroll
    for (int i = 0; i < 4; i++)
        #pragma unroll
        for (int j = 0; j < 4; j++) {
            const int c = n0 + nw * 32 + j * 8 + 2 * tig;
            const float2 bv = *(const float2*)(bias + c);
            #pragma unroll
            for (int hr = 0; hr < 2; hr++) {
                const int r = m0 + mw * 64 + i * 16 + group + hr * 8;
                const float o0 = (acc[i][j][2 * hr + 0] + bv.x) * (EPI == 2 ? qmask[r] : scale);
                const float o1 = (acc[i][j][2 * hr + 1] + bv.y) * (EPI == 2 ? qmask[r] : scale);
                if (EPI == 2) {
                    *(float2*)(Yf + (size_t)r * Dm + c) = make_float2(o0, o1);
                } else if (EPI == 0) {
                    const int h = c >> 6, d = c & 63;
                    const int bb = r >> 11, l = r & (Ls - 1);
                    __nv_bfloat16 h0, h1, l0, l1;
                    split1(o0, h0, l0); split1(o1, h1, l1);
                    const size_t idx = ((size_t)(bb * Hh + h) * Ls + l) * DPH + d;
                    __nv_bfloat162 ph; ph.x = h0; ph.y = h1;
                    __nv_bfloat162 pl; pl.x = l0; pl.y = l1;
                    *(__nv_bfloat162*)((__nv_bfloat16*)Yhi_ + idx) = ph;
                    *(__nv_bfloat162*)((__nv_bfloat16*)Ylo_ + idx) = pl;
                } else {
                    const int h = c >> 6, d = c & 63;
                    const int bb = r >> 11, l = r & (Ls - 1);
                    __half h0, h1, l0, l1;
                    split1h(o0, h0, l0); split1h(o1, h1, l1);
                    const size_t idx = ((size_t)(bb * Hh + h) * DPH + d) * Ls + l;
                    ((__half*)Yhi_)[idx] = h0; ((__half*)Ylo_)[idx] = l0;
                    ((__half*)Yhi_)[idx + Ls] = h1; ((__half*)Ylo_)[idx + Ls] = l1;
                }
            }
        }
}

// =====================================================================================
// Fused QK + exp + z. bh = bh0 + blockIdx.y (per-batch launches).
// =====================================================================================
__global__ void __launch_bounds__(256, 2) qk_kernel(int bh0)
{
    extern __shared__ char smraw[];
    char* sQhi = smraw;
    char* sQlo = smraw + 16384;
    char* sK   = smraw + 32768;                     // [stage][hi 16384 | lo 16384]
    float* red_z = (float*)(smraw + 98304);

    const int tid = threadIdx.x, wid = tid >> 5, lane = tid & 31;
    const int mw = wid >> 2, nw = wid & 3;
    const int m0 = blockIdx.x * 128;
    const int bh = bh0 + blockIdx.y;
    const int b = bh >> 4;
    const int group = lane >> 2, tig = lane & 3;
    const __nv_bfloat16* Qhi = g_qhi + (size_t)bh * Ls * DPH;
    const __nv_bfloat16* Qlo = g_qlo + (size_t)bh * Ls * DPH;
    const __nv_bfloat16* Khi = g_khi + (size_t)bh * Ls * DPH;
    const __nv_bfloat16* Klo = g_klo + (size_t)bh * Ls * DPH;

    #pragma unroll
    for (int i = 0; i < 4; i++) {
        const int lin = tid + i * 256;
        const int r = lin >> 3, ch = lin & 7;
        const uint32_t off = SW(r * 128 + ch * 16);
        cpasync16(sQhi + off, Qhi + (size_t)(m0 + r) * DPH + ch * 8);
        cpasync16(sQlo + off, Qlo + (size_t)(m0 + r) * DPH + ch * 8);
    }

    auto kload = [&](int s, int n0) {
        char* khb = sK + s * 32768;
        char* klb = khb + 16384;
        #pragma unroll
        for (int i = 0; i < 4; i++) {
            const int lin = tid + i * 256;
            const int r = lin >> 3, ch = lin & 7;
            const uint32_t off = SW(r * 128 + ch * 16);
            cpasync16(khb + off, Khi + (size_t)(n0 + r) * DPH + ch * 8);
            cpasync16(klb + off, Klo + (size_t)(n0 + r) * DPH + ch * 8);
        }
        CP_COMMIT();
    };
    kload(0, 0);

    float zloc[4][2] = {};
    const uint32_t qhi_a = saddr(sQhi), qlo_a = saddr(sQlo);

    for (int nt = 0; nt < Ls / 128; nt++) {
        const int n0 = nt * 128;
        CP_WAIT0();
        __syncthreads();
        if (nt < Ls / 128 - 1) kload((nt + 1) & 1, n0 + 128);

        uint32_t mb[4][2];
        #pragma unroll
        for (int i = 0; i < 4; i++)
            #pragma unroll
            for (int hr = 0; hr < 2; hr++) {
                const int r = m0 + mw * 64 + i * 16 + group + hr * 8;
                mb[i][hr] = g_mbits[(size_t)(b * Ls + r) * (Ls / 32) + ((n0 + nw * 32) >> 5)];
            }

        const uint32_t khi_a = saddr(sK + (nt & 1) * 32768);
        const uint32_t klo_a = khi_a + 16384;

        float acc[4][4][4] = {};
        #pragma unroll
        for (int kk = 0; kk < DPH; kk += 16) {
            uint32_t ah[4][4], al[4][4], bh2[4][2], bl[4][2];
            const int arow = mw * 64 + ((lane >> 3) & 1) * 8 + (lane & 7);
            const int acol = kk + (lane >> 4) * 8;
            #pragma unroll
            for (int i = 0; i < 4; i++) {
                const uint32_t o = SW((arow + i * 16) * 128 + acol * 2);
                ldsm4(qhi_a + o, ah[i]);
                ldsm4(qlo_a + o, al[i]);
            }
            const int brow = nw * 32 + (lane >> 4) * 8 + (lane & 7);
            const int bcol = kk + ((lane >> 3) & 1) * 8;
            #pragma unroll
            for (int jj = 0; jj < 2; jj++) {
                const uint32_t o = SW((brow + jj * 16) * 128 + bcol * 2);
                uint32_t t[4];
                ldsm4(khi_a + o, t);
                bh2[2 * jj][0] = t[0]; bh2[2 * jj][1] = t[1];
                bh2[2 * jj + 1][0] = t[2]; bh2[2 * jj + 1][1] = t[3];
                ldsm4(klo_a + o, t);
                bl[2 * jj][0] = t[0]; bl[2 * jj][1] = t[1];
                bl[2 * jj + 1][0] = t[2]; bl[2 * jj + 1][1] = t[3];
            }
            #pragma unroll
            for (int i = 0; i < 4; i++)
                #pragma unroll
                for (int j = 0; j < 4; j++) {
                    mma16816(acc[i][j], ah[i], bh2[j]);
                    mma16816(acc[i][j], ah[i], bl[j]);
                    mma16816(acc[i][j], al[i], bh2[j]);
                }
        }

        #pragma unroll
        for (int i = 0; i < 4; i++)
            #pragma unroll
            for (int hr = 0; hr < 2; hr++) {
                const int r = m0 + mw * 64 + i * 16 + group + hr * 8;
                const uint32_t bits = mb[i][hr];
                float zadd = 0.f;
                #pragma unroll
                for (int j = 0; j < 4; j++) {
                    const int c = n0 + nw * 32 + j * 8 + 2 * tig;
                    const int bpos = j * 8 + 2 * tig;
                    const float e0 = ((bits >> bpos) & 1u) ? 0.f : __expf(acc[i][j][2 * hr + 0]);
                    const float e1 = ((bits >> (bpos + 1)) & 1u) ? 0.f : __expf(acc[i][j][2 * hr + 1]);
                    const size_t so = ((size_t)bh * Ls + r) * Ls + c;
                    *(__half2*)(g_pe + so) = __floats2half2_rn(e0, e1);
                    zadd += e0 + e1;
                }
                zloc[i][hr] += zadd;
            }
    }

    #pragma unroll
    for (int i = 0; i < 4; i++)
        #pragma unroll
        for (int hr = 0; hr < 2; hr++) {
            float z = zloc[i][hr];
            z += __shfl_xor_sync(0xFFFFFFFFu, z, 1);
            z += __shfl_xor_sync(0xFFFFFFFFu, z, 2);
            if (tig == 0) {
                const int rloc = mw * 64 + i * 16 + hr * 8 + group;
                red_z[nw * 128 + rloc] = z;
            }
        }
    __syncthreads();
    if (tid < 128) {
        float z = red_z[tid] + red_z[128 + tid] + red_z[256 + tid] + red_z[384 + tid];
        g_iz[(size_t)bh * Ls + m0 + tid] = 1.f / z;
    }
}

// =====================================================================================
// avg: attn_avg[b,q,k] = qmask/Hh * sum_h e*iz_h.  Per-batch launches (b fixed).
// =====================================================================================
__global__ void __launch_bounds__(256) avg_kernel(const float* __restrict__ qmask,
                                                  float* __restrict__ avg_out, int b)
{
    const int tid = threadIdx.x;
    const int tx = tid & 15, ty = tid >> 4;
    const int k0 = blockIdx.x * 64;
    const int q0 = blockIdx.y * 64;

    float sum[4][4] = {};
    for (int h = 0; h < Hh; h++) {
        const int bhh = b * Hh + h;
        #pragma unroll
        for (int i = 0; i < 4; i++) {
            const int q = q0 + ty * 4 + i;
            const float iz = g_iz[(size_t)bhh * Ls + q];
            const size_t so = ((size_t)bhh * Ls + q) * Ls + k0 + tx * 4;
            const __half2 e01 = *(const __half2*)(g_pe + so);
            const __half2 e23 = *(const __half2*)(g_pe + so + 2);
            const float2 f01 = __half22float2(e01);
            const float2 f23 = __half22float2(e23);
            sum[i][0] = fmaf(f01.x, iz, sum[i][0]);
            sum[i][1] = fmaf(f01.y, iz, sum[i][1]);
            sum[i][2] = fmaf(f23.x, iz, sum[i][2]);
            sum[i][3] = fmaf(f23.y, iz, sum[i][3]);
        }
    }
    #pragma unroll
    for (int i = 0; i < 4; i++) {
        const int q = q0 + ty * 4 + i;
        const float qm = qmask[b * Ls + q] * (1.f / (float)Hh);
        float4 o;
        o.x = sum[i][0] * qm; o.y = sum[i][1] * qm; o.z = sum[i][2] * qm; o.w = sum[i][3] * qm;
        *(float4*)(avg_out + (size_t)(b * Ls + q) * Ls + k0 + tx * 4) = o;
    }
}

// =====================================================================================
// PV: C[128,64] = (E @ V^T) * iz. 3-stage single-sync pipeline. bh = bh0 + blockIdx.y.
// =====================================================================================
__global__ void __launch_bounds__(256, 2) pv_kernel(int bh0)
{
    extern __shared__ char smraw[];
    __half* sb = (__half*)smraw;
    const int PT = 128 * STR2;   // 9216
    const int VT = 64 * STR2;    // 4608
    const int STG = PT + 2 * VT; // 18432 halves per stage
    const int NC = Ls / 64;      // 32 chunks

    const int tid = threadIdx.x, wid = tid >> 5, lane = tid & 31;
    const int mw = wid >> 1, nw = wid & 1;
    const int m0 = blockIdx.x * 128;
    const int bh = bh0 + blockIdx.y;
    const int b = bh >> 4, h = bh & 15;
    const int group = lane >> 2, tig = lane & 3;
    const __half* Pe  = g_pe  + (size_t)bh * Ls * Ls;
    const __half* Vhi = g_vhi + (size_t)bh * DPH * Ls;
    const __half* Vlo = g_vlo + (size_t)bh * DPH * Ls;

    auto stage_load = [&](int s, int t0) {
        __half* base = sb + s * STG;
        #pragma unroll
        for (int i = 0; i < 4; i++) {
            const int lin = tid + i * 256;
            const int r = lin >> 3, c = lin & 7;
            cpasync16(base + r * STR2 + c * 8, Pe + (size_t)(m0 + r) * Ls + t0 + c * 8);
        }
        #pragma unroll
        for (int i = 0; i < 2; i++) {
            const int lin = tid + i * 256;
            const int r = lin >> 3, c = lin & 7;
            cpasync16(base + PT + r * STR2 + c * 8,      Vhi + (size_t)r * Ls + t0 + c * 8);
            cpasync16(base + PT + VT + r * STR2 + c * 8, Vlo + (size_t)r * Ls + t0 + c * 8);
        }
        CP_COMMIT();
    };
    stage_load(0, 0);
    stage_load(1, 64);

    float acc[2][4][4] = {};

    for (int kc = 0; kc < NC; kc++) {
        if (kc + 1 < NC) CP_WAIT1(); else CP_WAIT0();
        __syncthreads();
        if (kc + 2 < NC) stage_load((kc + 2) % 3, (kc + 2) * 64);
        __half* base = sb + (kc % 3) * STG;
        __half* sPe  = base;
        __half* sVhi = base + PT;
        __half* sVlo = base + PT + VT;
        #pragma unroll
        for (int kk = 0; kk < 64; kk += 16) {
            uint32_t ah[2][4], bh2[4][2], bl[4][2];
            const int arow = mw * 32 + ((lane >> 3) & 1) * 8 + (lane & 7);
            const int acol = kk + (lane >> 4) * 8;
            #pragma unroll
            for (int i = 0; i < 2; i++)
                ldsm4(saddr(sPe + (arow + i * 16) * STR2 + acol), ah[i]);
            const int brow = nw * 32 + (lane >> 4) * 8 + (lane & 7);
            const int bcol = kk + ((lane >> 3) & 1) * 8;
            #pragma unroll
            for (int jj = 0; jj < 2; jj++) {
                uint32_t t[4];
                ldsm4(saddr(sVhi + (brow + jj * 16) * STR2 + bcol), t);
                bh2[2 * jj][0] = t[0]; bh2[2 * jj][1] = t[1];
                bh2[2 * jj + 1][0] = t[2]; bh2[2 * jj + 1][1] = t[3];
                ldsm4(saddr(sVlo + (brow + jj * 16) * STR2 + bcol), t);
                bl[2 * jj][0] = t[0]; bl[2 * jj][1] = t[1];
                bl[2 * jj + 1][0] = t[2]; bl[2 * jj + 1][1] = t[3];
            }
            #pragma unroll
            for (int i = 0; i < 2; i++)
                #pragma unroll
                for (int j = 0; j < 4; j++) {
                    mma16816h(acc[i][j], ah[i], bh2[j]);
                    mma16816h(acc[i][j], ah[i], bl[j]);
                }
        }
    }

    float izv[2][2];
    #pragma unroll
    for (int i = 0; i < 2; i++)
        #pragma unroll
        for (int hr = 0; hr < 2; hr++) {
            const int r = m0 + mw * 32 + i * 16 + group + hr * 8;
            izv[i][hr] = g_iz[(size_t)bh * Ls + r];
        }

    #pragma unroll
    for (int i = 0; i < 2; i++)
        #pragma unroll
        for (int j = 0; j < 4; j++) {
            const int c = nw * 32 + j * 8 + 2 * tig;
            #pragma unroll
            for (int hr = 0; hr < 2; hr++) {
                const int r = m0 + mw * 32 + i * 16 + group + hr * 8;
                const size_t idx = (size_t)(b * Ls + r) * Dm + h * 64 + c;
                __nv_bfloat16 h0, h1, l0, l1;
                split1(acc[i][j][2 * hr + 0] * izv[i][hr], h0, l0);
                split1(acc[i][j][2 * hr + 1] * izv[i][hr], h1, l1);
                __nv_bfloat162 ph; ph.x = h0; ph.y = h1;
                __nv_bfloat162 pl; pl.x = l0; pl.y = l1;
                *(__nv_bfloat162*)(g_chi + idx) = ph;
                *(__nv_bfloat162*)(g_clo + idx) = pl;
            }
        }
}

// =====================================================================================
// Launch — batch-pipelined DAG across 4 streams (all side streams forked from main
// BEFORE first use: graph-capture requirement).
// main: convsplits, kproj, qk0..qk3, join
// s2:   qproj, then pv_b (after qk_b)
// s3:   vproj, then fin_b (after pv_b)
// s4:   packmask, then avg_b (after qk_b)
// =====================================================================================
extern "C" void kernel_launch(void* const* d_in, const int* in_sizes, int n_in,
                              void* d_out, int out_size)
{
    (void)in_sizes; (void)n_in; (void)out_size;
    const float* k_in  = (const float*)d_in[0];
    const float* v_in  = (const float*)d_in[1];
    const float* q_in  = (const float*)d_in[2];
    const int*   amask = (const int*)  d_in[3];
    const float* qmask = (const float*)d_in[4];
    const float* kqv_w = (const float*)d_in[5];
    const float* kqv_b = (const float*)d_in[6];
    const float* fin_w = (const float*)d_in[7];
    const float* fin_b = (const float*)d_in[8];
    float* out_ctx = (float*)d_out;
    float* out_avg = out_ctx + (size_t)Bb * Ls * Dm;

    __nv_bfloat16 *xhi, *xlo, *whi, *wlo, *qhi, *qlo, *khi, *klo, *chi, *clo;
    __half *vhi, *vlo;
    cudaGetSymbolAddress((void**)&xhi, g_xhi); cudaGetSymbolAddress((void**)&xlo, g_xlo);
    cudaGetSymbolAddress((void**)&whi, g_whi); cudaGetSymbolAddress((void**)&wlo, g_wlo);
    cudaGetSymbolAddress((void**)&qhi, g_qhi); cudaGetSymbolAddress((void**)&qlo, g_qlo);
    cudaGetSymbolAddress((void**)&khi, g_khi); cudaGetSymbolAddress((void**)&klo, g_klo);
    cudaGetSymbolAddress((void**)&vhi, g_vhi); cudaGetSymbolAddress((void**)&vlo, g_vlo);
    cudaGetSymbolAddress((void**)&chi, g_chi); cudaGetSymbolAddress((void**)&clo, g_clo);

    const int GSM  = 2 * 4 * 128 * STR * 2;                  // 81920 B
    const int QKSM = 98304 + 4 * 128 * 4;                    // 100352 B
    const int PVSM = 3 * (128 * STR2 + 2 * 64 * STR2) * 2;   // 110592 B
    static int attr_set = 0;
    static cudaStream_t s2 = nullptr, s3 = nullptr, s4 = nullptr;
    static cudaEvent_t evFork0, evPM, evQ, evV;
    static cudaEvent_t evQK[Bb], evPV[Bb], evFin[Bb], evAvg[Bb];
    if (!attr_set) {
        cudaFuncSetAttribute(gemm_bf<0>, cudaFuncAttributeMaxDynamicSharedMemorySize, GSM);
        cudaFuncSetAttribute(gemm_bf<1>, cudaFuncAttributeMaxDynamicSharedMemorySize, GSM);
        cudaFuncSetAttribute(gemm_bf<2>, cudaFuncAttributeMaxDynamicSharedMemorySize, GSM);
        cudaFuncSetAttribute(qk_kernel,  cudaFuncAttributeMaxDynamicSharedMemorySize, QKSM);
        cudaFuncSetAttribute(pv_kernel,  cudaFuncAttributeMaxDynamicSharedMemorySize, PVSM);
        cudaStreamCreateWithFlags(&s2, cudaStreamNonBlocking);
        cudaStreamCreateWithFlags(&s3, cudaStreamNonBlocking);
        cudaStreamCreateWithFlags(&s4, cudaStreamNonBlocking);
        cudaEventCreateWithFlags(&evFork0, cudaEventDisableTiming);
        cudaEventCreateWithFlags(&evPM,    cudaEventDisableTiming);
        cudaEventCreateWithFlags(&evQ,     cudaEventDisableTiming);
        cudaEventCreateWithFlags(&evV,     cudaEventDisableTiming);
        for (int i = 0; i < Bb; i++) {
            cudaEventCreateWithFlags(&evQK[i],  cudaEventDisableTiming);
            cudaEventCreateWithFlags(&evPV[i],  cudaEventDisableTiming);
            cudaEventCreateWithFlags(&evFin[i], cudaEventDisableTiming);
            cudaEventCreateWithFlags(&evAvg[i], cudaEventDisableTiming);
        }
        attr_set = 1;
    }

    const int NIN = 8388608;
    dim3 gg(Dm / 128, (Bb * Ls) / 128);    // (8, 64)
    dim3 ggb(Dm / 128, 16);                // per-batch fin grid

    // ---- fork ALL side streams from main at t=0 (capture-legal) ----
    cudaEventRecord(evFork0, 0);
    cudaStreamWaitEvent(s2, evFork0, 0);
    cudaStreamWaitEvent(s3, evFork0, 0);
    cudaStreamWaitEvent(s4, evFork0, 0);

    // packmask on s4 (concurrent with convsplits on main)
    packmask<<<(Bb * Ls * Ls / 32) / 256, 256, 0, s4>>>(amask);
    cudaEventRecord(evPM, s4);

    // prologue on main
    convsplit3<<<dim3(NIN / 1024, 3), 256>>>(k_in, v_in, q_in, xhi, xlo);
    convsplit<<<(3 * 1048576) / 1024, 256>>>(kqv_w, whi,              wlo);
    convsplit<<<1048576 / 1024, 256>>>(fin_w, whi + 3 * 1048576, wlo + 3 * 1048576);
    cudaEventRecord(evFork0, 0);   // re-record: conv outputs now ready
    cudaStreamWaitEvent(s2, evFork0, 0);
    cudaStreamWaitEvent(s3, evFork0, 0);

    // projections: k (main) || q (s2) || v (s3)
    gemm_bf<0><<<gg, 256, GSM>>>(xhi, xlo, whi, wlo, kqv_b, nullptr, 1.0f, 0, khi, klo, nullptr);
    gemm_bf<0><<<gg, 256, GSM, s2>>>(xhi + 2 * NIN, xlo + 2 * NIN, whi + 1048576, wlo + 1048576,
                                     kqv_b + Dm, nullptr, 0.125f, 0, qhi, qlo, nullptr);
    cudaEventRecord(evQ, s2);
    gemm_bf<1><<<gg, 256, GSM, s3>>>(xhi + NIN, xlo + NIN, whi + 2 * 1048576, wlo + 2 * 1048576,
                                     kqv_b + 2 * Dm, nullptr, 1.0f, 0, vhi, vlo, nullptr);
    cudaEventRecord(evV, s3);

    // qk needs qproj + packmask (kproj ordered on main)
    cudaStreamWaitEvent(0, evQ, 0);
    cudaStreamWaitEvent(0, evPM, 0);
    // pv (s2) needs vproj once
    cudaStreamWaitEvent(s2, evV, 0);

    for (int b = 0; b < Bb; b++) {
        qk_kernel<<<dim3(Ls / 128, Hh), 256, QKSM>>>(b * Hh);
        cudaEventRecord(evQK[b], 0);

        cudaStreamWaitEvent(s2, evQK[b], 0);
        pv_kernel<<<dim3(Ls / 128, Hh), 256, PVSM, s2>>>(b * Hh);
        cudaEventRecord(evPV[b], s2);

        cudaStreamWaitEvent(s3, evPV[b], 0);
        gemm_bf<2><<<ggb, 256, GSM, s3>>>(chi, clo, whi + 3 * 1048576, wlo + 3 * 1048576,
                                          fin_b, qmask, 1.0f, b * 16, nullptr, nullptr, out_ctx);
        cudaEventRecord(evFin[b], s3);

        cudaStreamWaitEvent(s4, evQK[b], 0);
        avg_kernel<<<dim3(Ls / 64, Ls / 64), 256, 0, s4>>>(qmask, out_avg, b);
        cudaEventRecord(evAvg[b], s4);
    }

    for (int b = 0; b < Bb; b++) {
        cudaStreamWaitEvent(0, evFin[b], 0);
        cudaStreamWaitEvent(0, evAvg[b], 0);
    }
}